// round 2
// baseline (speedup 1.0000x reference)
#include <cuda_runtime.h>

#define DIM   768
#define HEADS 12
#define HDIM  64
#define SEQ   1024
#define BATCH 8
#define ROWS  (BATCH*SEQ)   // 8192
#define LN_EPS 1e-5f

// ---------------- scratch (device globals: no allocation allowed) ----------------
__device__ float g_xnorm[ROWS*DIM];
__device__ float g_Q[ROWS*DIM];      // (B,H,N,D)
__device__ float g_K[ROWS*DIM];      // (B,H,N,D)
__device__ float g_V[ROWS*DIM];      // (B,H,N,D)
__device__ float g_attn[ROWS*DIM];   // (B,N,C)

// ---------------- LayerNorm ----------------
__global__ __launch_bounds__(256) void ln_kernel(const float* __restrict__ x,
                                                 const float* __restrict__ gamma,
                                                 const float* __restrict__ beta) {
    int row = blockIdx.x;
    const float* xr = x + (size_t)row * DIM;
    float s = 0.f, sq = 0.f;
    for (int c = threadIdx.x; c < DIM; c += 256) { float v = xr[c]; s += v; sq += v * v; }
    #pragma unroll
    for (int o = 16; o > 0; o >>= 1) {
        s  += __shfl_xor_sync(0xffffffffu, s, o);
        sq += __shfl_xor_sync(0xffffffffu, sq, o);
    }
    __shared__ float ws[8], wsq[8];
    int w = threadIdx.x >> 5;
    if ((threadIdx.x & 31) == 0) { ws[w] = s; wsq[w] = sq; }
    __syncthreads();
    s = 0.f; sq = 0.f;
    #pragma unroll
    for (int i = 0; i < 8; i++) { s += ws[i]; sq += wsq[i]; }
    float mu  = s * (1.0f / DIM);
    float var = sq * (1.0f / DIM) - mu * mu;
    float inv = rsqrtf(var + LN_EPS);
    float* o = g_xnorm + (size_t)row * DIM;
    for (int c = threadIdx.x; c < DIM; c += 256)
        o[c] = (xr[c] - mu) * inv * gamma[c] + beta[c];
}

// ---------------- tiled GEMM params ----------------
#define BM 128
#define BN 64
#define BK 16

// QKV projection: out = xnorm @ W + b ; z selects Q/K/V; Q adds pos_embed.
// Writes output in (B,H,N,D) layout.
__global__ __launch_bounds__(256) void qkv_gemm(
    const float* __restrict__ Wq, const float* __restrict__ bq,
    const float* __restrict__ Wk, const float* __restrict__ bk,
    const float* __restrict__ Wv, const float* __restrict__ bv,
    const float* __restrict__ pos) {
    const int which = blockIdx.z;
    const float* W    = (which == 0) ? Wq : ((which == 1) ? Wk : Wv);
    const float* bias = (which == 0) ? bq : ((which == 1) ? bk : bv);
    float* out        = (which == 0) ? g_Q : ((which == 1) ? g_K : g_V);

    __shared__ float As[BK][BM + 1];
    __shared__ float Bs[BK][BN];
    const int t  = threadIdx.x;
    const int tx = t & 15, ty = t >> 4;
    const int row0 = blockIdx.y * BM;
    const int col0 = blockIdx.x * BN;
    const int a_m = t >> 2;
    const int a_k = (t & 3) << 2;
    const int b_k = t >> 4;
    const int b_c = (t & 15) << 2;

    float acc[8][4];
    #pragma unroll
    for (int i = 0; i < 8; i++)
        #pragma unroll
        for (int j = 0; j < 4; j++) acc[i][j] = 0.f;

    for (int k0 = 0; k0 < DIM; k0 += BK) {
        float4 va = *(const float4*)&g_xnorm[(size_t)(row0 + a_m)      * DIM + k0 + a_k];
        float4 vb = *(const float4*)&g_xnorm[(size_t)(row0 + a_m + 64) * DIM + k0 + a_k];
        float4 wv = *(const float4*)&W[(size_t)(k0 + b_k) * DIM + col0 + b_c];
        As[a_k + 0][a_m] = va.x; As[a_k + 1][a_m] = va.y;
        As[a_k + 2][a_m] = va.z; As[a_k + 3][a_m] = va.w;
        As[a_k + 0][a_m + 64] = vb.x; As[a_k + 1][a_m + 64] = vb.y;
        As[a_k + 2][a_m + 64] = vb.z; As[a_k + 3][a_m + 64] = vb.w;
        *(float4*)&Bs[b_k][b_c] = wv;
        __syncthreads();
        #pragma unroll
        for (int kk = 0; kk < BK; kk++) {
            float a[8];
            #pragma unroll
            for (int i = 0; i < 8; i++) a[i] = As[kk][ty * 8 + i];
            float4 b4 = *(const float4*)&Bs[kk][tx * 4];
            float b[4] = {b4.x, b4.y, b4.z, b4.w};
            #pragma unroll
            for (int i = 0; i < 8; i++)
                #pragma unroll
                for (int j = 0; j < 4; j++)
                    acc[i][j] += a[i] * b[j];
        }
        __syncthreads();
    }

    #pragma unroll
    for (int i = 0; i < 8; i++) {
        int m = row0 + ty * 8 + i;
        int bidx = m >> 10;      // batch
        int n    = m & 1023;     // seq pos
        #pragma unroll
        for (int j = 0; j < 4; j++) {
            int c = col0 + tx * 4 + j;
            float v = acc[i][j] + bias[c];
            if (which == 0) v += pos[(size_t)m * DIM + c];
            int h = c >> 6, d = c & 63;
            out[(size_t)((bidx * HEADS + h) * SEQ + n) * HDIM + d] = v;
        }
    }
}

// Output projection + bias + residual: d_out = g_attn @ Wo + bo + x
__global__ __launch_bounds__(256) void out_gemm(
    const float* __restrict__ Wo, const float* __restrict__ bo,
    const float* __restrict__ x, float* __restrict__ out) {
    __shared__ float As[BK][BM + 1];
    __shared__ float Bs[BK][BN];
    const int t  = threadIdx.x;
    const int tx = t & 15, ty = t >> 4;
    const int row0 = blockIdx.y * BM;
    const int col0 = blockIdx.x * BN;
    const int a_m = t >> 2;
    const int a_k = (t & 3) << 2;
    const int b_k = t >> 4;
    const int b_c = (t & 15) << 2;

    float acc[8][4];
    #pragma unroll
    for (int i = 0; i < 8; i++)
        #pragma unroll
        for (int j = 0; j < 4; j++) acc[i][j] = 0.f;

    for (int k0 = 0; k0 < DIM; k0 += BK) {
        float4 va = *(const float4*)&g_attn[(size_t)(row0 + a_m)      * DIM + k0 + a_k];
        float4 vb = *(const float4*)&g_attn[(size_t)(row0 + a_m + 64) * DIM + k0 + a_k];
        float4 wv = *(const float4*)&Wo[(size_t)(k0 + b_k) * DIM + col0 + b_c];
        As[a_k + 0][a_m] = va.x; As[a_k + 1][a_m] = va.y;
        As[a_k + 2][a_m] = va.z; As[a_k + 3][a_m] = va.w;
        As[a_k + 0][a_m + 64] = vb.x; As[a_k + 1][a_m + 64] = vb.y;
        As[a_k + 2][a_m + 64] = vb.z; As[a_k + 3][a_m + 64] = vb.w;
        *(float4*)&Bs[b_k][b_c] = wv;
        __syncthreads();
        #pragma unroll
        for (int kk = 0; kk < BK; kk++) {
            float a[8];
            #pragma unroll
            for (int i = 0; i < 8; i++) a[i] = As[kk][ty * 8 + i];
            float4 b4 = *(const float4*)&Bs[kk][tx * 4];
            float b[4] = {b4.x, b4.y, b4.z, b4.w};
            #pragma unroll
            for (int i = 0; i < 8; i++)
                #pragma unroll
                for (int j = 0; j < 4; j++)
                    acc[i][j] += a[i] * b[j];
        }
        __syncthreads();
    }

    #pragma unroll
    for (int i = 0; i < 8; i++) {
        int m = row0 + ty * 8 + i;
        float4 xr = *(const float4*)&x[(size_t)m * DIM + col0 + tx * 4];
        float4 bb = *(const float4*)&bo[col0 + tx * 4];
        float4 r;
        r.x = acc[i][0] + bb.x + xr.x;
        r.y = acc[i][1] + bb.y + xr.y;
        r.z = acc[i][2] + bb.z + xr.z;
        r.w = acc[i][3] + bb.w + xr.w;
        *(float4*)&out[(size_t)m * DIM + col0 + tx * 4] = r;
    }
}

// ---------------- flash-style attention ----------------
// One block = one (b,h) x 64-query tile. Online softmax, K/V share one smem buffer.
#define ATTN_SMEM_FLOATS (64*65 + 64*68 + 64*65)
#define ATTN_SMEM_BYTES  (ATTN_SMEM_FLOATS * 4)

__global__ __launch_bounds__(256) void attn_kernel() {
    extern __shared__ float sm[];
    float* Qs = sm;                 // [64][65]  Q[m][k]
    float* KV = sm + 64 * 65;       // [64][68]  K phase: [k][n]; V phase: [n][d]
    float* Ss = KV + 64 * 68;       // [64][65]  scores / probabilities
    __shared__ float row_m[64], row_l[64], row_alpha[64];
    __shared__ float red[64][4];

    const int t  = threadIdx.x;
    const int tx = t & 15, ty = t >> 4;
    const int q0 = blockIdx.x * 64;
    const int bh = blockIdx.y;
    const float* Qg = g_Q + (size_t)bh * SEQ * HDIM;
    const float* Kg = g_K + (size_t)bh * SEQ * HDIM;
    const float* Vg = g_V + (size_t)bh * SEQ * HDIM;

    const int lr  = t >> 2;          // row 0..63 (4 threads per row)
    const int lc0 = (t & 3) * 16;    // col base: 0,16,32,48 (each thread: 16 floats)

    {   // load Q tile: full 64x64
        #pragma unroll
        for (int ii = 0; ii < 4; ii++) {
            int c = lc0 + ii * 4;
            float4 v = *(const float4*)&Qg[(size_t)(q0 + lr) * HDIM + c];
            Qs[lr * 65 + c + 0] = v.x; Qs[lr * 65 + c + 1] = v.y;
            Qs[lr * 65 + c + 2] = v.z; Qs[lr * 65 + c + 3] = v.w;
        }
    }
    if (t < 64) { row_m[t] = -1e30f; row_l[t] = 0.f; }

    float o[4][4];
    #pragma unroll
    for (int i = 0; i < 4; i++)
        #pragma unroll
        for (int j = 0; j < 4; j++) o[i][j] = 0.f;

    for (int n0 = 0; n0 < SEQ; n0 += 64) {
        {   // load K tile transposed: KV[k][n], full 64x64
            #pragma unroll
            for (int ii = 0; ii < 4; ii++) {
                int c = lc0 + ii * 4;
                float4 v = *(const float4*)&Kg[(size_t)(n0 + lr) * HDIM + c];
                KV[(c + 0) * 68 + lr] = v.x;
                KV[(c + 1) * 68 + lr] = v.y;
                KV[(c + 2) * 68 + lr] = v.z;
                KV[(c + 3) * 68 + lr] = v.w;
            }
        }
        __syncthreads();

        // S = Q @ K^T * (1/8)
        float s4[4][4];
        #pragma unroll
        for (int i = 0; i < 4; i++)
            #pragma unroll
            for (int j = 0; j < 4; j++) s4[i][j] = 0.f;
        #pragma unroll 8
        for (int kk = 0; kk < 64; kk++) {
            float a0 = Qs[(ty * 4 + 0) * 65 + kk];
            float a1 = Qs[(ty * 4 + 1) * 65 + kk];
            float a2 = Qs[(ty * 4 + 2) * 65 + kk];
            float a3 = Qs[(ty * 4 + 3) * 65 + kk];
            float4 b4 = *(const float4*)&KV[kk * 68 + tx * 4];
            s4[0][0] += a0 * b4.x; s4[0][1] += a0 * b4.y; s4[0][2] += a0 * b4.z; s4[0][3] += a0 * b4.w;
            s4[1][0] += a1 * b4.x; s4[1][1] += a1 * b4.y; s4[1][2] += a1 * b4.z; s4[1][3] += a1 * b4.w;
            s4[2][0] += a2 * b4.x; s4[2][1] += a2 * b4.y; s4[2][2] += a2 * b4.z; s4[2][3] += a2 * b4.w;
            s4[3][0] += a3 * b4.x; s4[3][1] += a3 * b4.y; s4[3][2] += a3 * b4.z; s4[3][3] += a3 * b4.w;
        }
        #pragma unroll
        for (int i = 0; i < 4; i++)
            #pragma unroll
            for (int j = 0; j < 4; j++)
                Ss[(ty * 4 + i) * 65 + tx * 4 + j] = s4[i][j] * 0.125f;
        __syncthreads();

        // phase A: overlap V global load with partial row-max; V overwrites K in KV
        {
            float4 vload[4];
            #pragma unroll
            for (int ii = 0; ii < 4; ii++)
                vload[ii] = *(const float4*)&Vg[(size_t)(n0 + lr) * HDIM + lc0 + ii * 4];
            int r = t >> 2, q = t & 3;
            float pmax = -1e30f;
            #pragma unroll
            for (int cc = 0; cc < 16; cc++)
                pmax = fmaxf(pmax, Ss[r * 65 + q * 16 + cc]);
            #pragma unroll
            for (int ii = 0; ii < 4; ii++)
                *(float4*)&KV[lr * 68 + lc0 + ii * 4] = vload[ii];   // V[n][d]
            red[r][q] = pmax;
        }
        __syncthreads();

        if (t < 64) {
            float mx = fmaxf(fmaxf(red[t][0], red[t][1]), fmaxf(red[t][2], red[t][3]));
            float mold = row_m[t];
            float mnew = fmaxf(mold, mx);
            row_m[t] = mnew;
            row_alpha[t] = __expf(mold - mnew);
        }
        __syncthreads();

        {   // exponentiate in place + partial sums
            int r = t >> 2, q = t & 3;
            float mnew = row_m[r];
            float ps = 0.f;
            #pragma unroll
            for (int cc = 0; cc < 16; cc++) {
                int idx = r * 65 + q * 16 + cc;
                float e = __expf(Ss[idx] - mnew);
                Ss[idx] = e;
                ps += e;
            }
            red[r][q] = ps;
        }
        __syncthreads();

        if (t < 64)
            row_l[t] = row_l[t] * row_alpha[t] + (red[t][0] + red[t][1] + red[t][2] + red[t][3]);

        // O = O*alpha + P @ V
        #pragma unroll
        for (int i = 0; i < 4; i++) {
            float al = row_alpha[ty * 4 + i];
            #pragma unroll
            for (int j = 0; j < 4; j++) o[i][j] *= al;
        }
        #pragma unroll 8
        for (int n = 0; n < 64; n++) {
            float4 v4 = *(const float4*)&KV[n * 68 + tx * 4];
            float p0 = Ss[(ty * 4 + 0) * 65 + n];
            float p1 = Ss[(ty * 4 + 1) * 65 + n];
            float p2 = Ss[(ty * 4 + 2) * 65 + n];
            float p3 = Ss[(ty * 4 + 3) * 65 + n];
            o[0][0] += p0 * v4.x; o[0][1] += p0 * v4.y; o[0][2] += p0 * v4.z; o[0][3] += p0 * v4.w;
            o[1][0] += p1 * v4.x; o[1][1] += p1 * v4.y; o[1][2] += p1 * v4.z; o[1][3] += p1 * v4.w;
            o[2][0] += p2 * v4.x; o[2][1] += p2 * v4.y; o[2][2] += p2 * v4.z; o[2][3] += p2 * v4.w;
            o[3][0] += p3 * v4.x; o[3][1] += p3 * v4.y; o[3][2] += p3 * v4.z; o[3][3] += p3 * v4.w;
        }
        __syncthreads();
    }

    // write back to (B,N,C)
    const int b = bh / HEADS;
    const int h = bh % HEADS;
    #pragma unroll
    for (int i = 0; i < 4; i++) {
        int m = ty * 4 + i;
        float invl = 1.0f / row_l[m];
        float4 r;
        r.x = o[i][0] * invl; r.y = o[i][1] * invl;
        r.z = o[i][2] * invl; r.w = o[i][3] * invl;
        *(float4*)&g_attn[(size_t)(b * SEQ + q0 + m) * DIM + h * HDIM + tx * 4] = r;
    }
}

// ---------------- launcher ----------------
extern "C" void kernel_launch(void* const* d_in, const int* in_sizes, int n_in,
                              void* d_out, int out_size) {
    const float* x     = (const float*)d_in[0];
    const float* pos   = (const float*)d_in[1];
    const float* gamma = (const float*)d_in[2];
    const float* beta  = (const float*)d_in[3];
    const float* Wq    = (const float*)d_in[4];
    const float* bq    = (const float*)d_in[5];
    const float* Wk    = (const float*)d_in[6];
    const float* bk    = (const float*)d_in[7];
    const float* Wv    = (const float*)d_in[8];
    const float* bv    = (const float*)d_in[9];
    const float* Wo    = (const float*)d_in[10];
    const float* bo    = (const float*)d_in[11];
    float* out = (float*)d_out;

    cudaFuncSetAttribute(attn_kernel, cudaFuncAttributeMaxDynamicSharedMemorySize, 64 * 1024);

    ln_kernel<<<ROWS, 256>>>(x, gamma, beta);
    qkv_gemm<<<dim3(DIM / BN, ROWS / BM, 3), 256>>>(Wq, bq, Wk, bk, Wv, bv, pos);
    attn_kernel<<<dim3(SEQ / 64, BATCH * HEADS), 256, ATTN_SMEM_BYTES>>>();
    out_gemm<<<dim3(DIM / BN, ROWS / BM), 256>>>(Wo, bo, x, out);
}

// round 3
// speedup vs baseline: 1.3607x; 1.3607x over previous
#include <cuda_runtime.h>
#include <cstdint>

#define DIM   768
#define HEADS 12
#define HDIM  64
#define SEQ   1024
#define BATCH 8
#define ROWS  (BATCH*SEQ)   // 8192
#define LN_EPS 1e-5f

// ---------------- scratch ----------------
__device__ float g_xnorm[ROWS*DIM];
__device__ float g_Q[ROWS*DIM];      // (B,H,N,D)
__device__ float g_K[ROWS*DIM];      // (B,H,N,D)
__device__ float g_V[ROWS*DIM];      // (B,H,N,D)
__device__ float g_attn[ROWS*DIM];   // (B,N,C)

// ---------------- LayerNorm ----------------
__global__ __launch_bounds__(256) void ln_kernel(const float* __restrict__ x,
                                                 const float* __restrict__ gamma,
                                                 const float* __restrict__ beta) {
    int row = blockIdx.x;
    const float* xr = x + (size_t)row * DIM;
    float s = 0.f, sq = 0.f;
    for (int c = threadIdx.x; c < DIM; c += 256) { float v = xr[c]; s += v; sq += v * v; }
    #pragma unroll
    for (int o = 16; o > 0; o >>= 1) {
        s  += __shfl_xor_sync(0xffffffffu, s, o);
        sq += __shfl_xor_sync(0xffffffffu, sq, o);
    }
    __shared__ float ws[8], wsq[8];
    int w = threadIdx.x >> 5;
    if ((threadIdx.x & 31) == 0) { ws[w] = s; wsq[w] = sq; }
    __syncthreads();
    s = 0.f; sq = 0.f;
    #pragma unroll
    for (int i = 0; i < 8; i++) { s += ws[i]; sq += wsq[i]; }
    float mu  = s * (1.0f / DIM);
    float var = sq * (1.0f / DIM) - mu * mu;
    float inv = rsqrtf(var + LN_EPS);
    float* o = g_xnorm + (size_t)row * DIM;
    for (int c = threadIdx.x; c < DIM; c += 256)
        o[c] = (xr[c] - mu) * inv * gamma[c] + beta[c];
}

// ---------------- tf32 tensor-core GEMM ----------------
// Block tile 128x128, BK=16, 256 threads = 8 warps in 2x4 (warp tile 64x32).
#define GBM 128
#define GBN 128
#define GBK 16
#define LDS_PAD 8
#define LDK (GBM + LDS_PAD)   // 136, used for both As and Bs row stride

#define MMA_TF32(c, a, b) \
  asm volatile("mma.sync.aligned.m16n8k8.row.col.f32.tf32.tf32.f32 " \
    "{%0,%1,%2,%3}, {%4,%5,%6,%7}, {%8,%9}, {%0,%1,%2,%3};" \
    : "+f"((c)[0]), "+f"((c)[1]), "+f"((c)[2]), "+f"((c)[3]) \
    : "r"((a)[0]), "r"((a)[1]), "r"((a)[2]), "r"((a)[3]), "r"((b)[0]), "r"((b)[1]))

// Mainloop: C[128x128] tile of A(row-major, lda=DIM) @ B(row-major k x n, ldb=DIM).
// c[i][j][4]: i = m-frag (16 rows each), j = n-frag (8 cols each).
__device__ __forceinline__ void gemm_tf32_mainloop(
    const float* __restrict__ A, const float* __restrict__ B,
    int row0, int col0, float c[4][4][4], float* As, float* Bs) {
    const int t    = threadIdx.x;
    const int lane = t & 31;
    const int warp = t >> 5;
    const int wr   = warp >> 2;       // 0..1
    const int wc   = warp & 3;        // 0..3
    const int lq   = lane & 3;        // thread-in-group
    const int lg   = lane >> 2;       // group id

    const int a_m = t >> 1;           // 0..127
    const int a_k = (t & 1) * 8;      // 0 or 8
    const int b_k = t >> 4;           // 0..15
    const int b_n = (t & 15) * 8;     // 0..120

    float4 pa0 = *(const float4*)&A[(size_t)(row0 + a_m) * DIM + a_k];
    float4 pa1 = *(const float4*)&A[(size_t)(row0 + a_m) * DIM + a_k + 4];
    float4 pb0 = *(const float4*)&B[(size_t)b_k * DIM + col0 + b_n];
    float4 pb1 = *(const float4*)&B[(size_t)b_k * DIM + col0 + b_n + 4];

    for (int k0 = 0; k0 < DIM; k0 += GBK) {
        // stage to smem (A transposed: As[k][m])
        As[(a_k + 0) * LDK + a_m] = pa0.x;
        As[(a_k + 1) * LDK + a_m] = pa0.y;
        As[(a_k + 2) * LDK + a_m] = pa0.z;
        As[(a_k + 3) * LDK + a_m] = pa0.w;
        As[(a_k + 4) * LDK + a_m] = pa1.x;
        As[(a_k + 5) * LDK + a_m] = pa1.y;
        As[(a_k + 6) * LDK + a_m] = pa1.z;
        As[(a_k + 7) * LDK + a_m] = pa1.w;
        *(float4*)&Bs[b_k * LDK + b_n]     = pb0;
        *(float4*)&Bs[b_k * LDK + b_n + 4] = pb1;
        __syncthreads();

        // prefetch next tile
        if (k0 + GBK < DIM) {
            pa0 = *(const float4*)&A[(size_t)(row0 + a_m) * DIM + k0 + GBK + a_k];
            pa1 = *(const float4*)&A[(size_t)(row0 + a_m) * DIM + k0 + GBK + a_k + 4];
            pb0 = *(const float4*)&B[(size_t)(k0 + GBK + b_k) * DIM + col0 + b_n];
            pb1 = *(const float4*)&B[(size_t)(k0 + GBK + b_k) * DIM + col0 + b_n + 4];
        }

        #pragma unroll
        for (int ks = 0; ks < 2; ks++) {
            const int kb = ks * 8;
            uint32_t af[4][4], bf[4][2];
            #pragma unroll
            for (int i = 0; i < 4; i++) {
                int m = wr * 64 + i * 16 + lg;
                af[i][0] = __float_as_uint(As[(kb + lq)     * LDK + m]);
                af[i][1] = __float_as_uint(As[(kb + lq)     * LDK + m + 8]);
                af[i][2] = __float_as_uint(As[(kb + lq + 4) * LDK + m]);
                af[i][3] = __float_as_uint(As[(kb + lq + 4) * LDK + m + 8]);
            }
            #pragma unroll
            for (int j = 0; j < 4; j++) {
                int n = wc * 32 + j * 8 + lg;
                bf[j][0] = __float_as_uint(Bs[(kb + lq)     * LDK + n]);
                bf[j][1] = __float_as_uint(Bs[(kb + lq + 4) * LDK + n]);
            }
            #pragma unroll
            for (int i = 0; i < 4; i++)
                #pragma unroll
                for (int j = 0; j < 4; j++)
                    MMA_TF32(c[i][j], af[i], bf[j]);
        }
        __syncthreads();
    }
}

// QKV projection: out = xnorm @ W + b; z selects Q/K/V; Q adds pos. Output (B,H,N,D).
__global__ __launch_bounds__(256, 1) void qkv_gemm_tc(
    const float* __restrict__ Wq, const float* __restrict__ bq,
    const float* __restrict__ Wk, const float* __restrict__ bk,
    const float* __restrict__ Wv, const float* __restrict__ bv,
    const float* __restrict__ pos) {
    __shared__ float As[GBK * LDK];
    __shared__ float Bs[GBK * LDK];
    const int which = blockIdx.z;
    const float* W    = (which == 0) ? Wq : ((which == 1) ? Wk : Wv);
    const float* bias = (which == 0) ? bq : ((which == 1) ? bk : bv);
    float* out        = (which == 0) ? g_Q : ((which == 1) ? g_K : g_V);

    const int row0 = blockIdx.y * GBM;
    const int col0 = blockIdx.x * GBN;

    float c[4][4][4];
    #pragma unroll
    for (int i = 0; i < 4; i++)
        #pragma unroll
        for (int j = 0; j < 4; j++)
            #pragma unroll
            for (int q = 0; q < 4; q++) c[i][j][q] = 0.f;

    gemm_tf32_mainloop(g_xnorm, W, row0, col0, c, As, Bs);

    const int lane = threadIdx.x & 31;
    const int warp = threadIdx.x >> 5;
    const int wr = warp >> 2, wc = warp & 3;
    const int lq = lane & 3, lg = lane >> 2;

    #pragma unroll
    for (int i = 0; i < 4; i++) {
        #pragma unroll
        for (int j = 0; j < 4; j++) {
            int cc = col0 + wc * 32 + j * 8 + 2 * lq;
            float b0 = bias[cc], b1 = bias[cc + 1];
            int h = cc >> 6, d = cc & 63;
            #pragma unroll
            for (int rh = 0; rh < 2; rh++) {
                int m = row0 + wr * 64 + i * 16 + lg + rh * 8;
                float v0 = c[i][j][rh * 2 + 0] + b0;
                float v1 = c[i][j][rh * 2 + 1] + b1;
                if (which == 0) {
                    float2 p = *(const float2*)&pos[(size_t)m * DIM + cc];
                    v0 += p.x; v1 += p.y;
                }
                int bidx = m >> 10, n = m & 1023;
                float2 r = make_float2(v0, v1);
                *(float2*)&out[(size_t)((bidx * HEADS + h) * SEQ + n) * HDIM + d] = r;
            }
        }
    }
}

// Out projection + bias + residual: d_out = g_attn @ Wo + bo + x
__global__ __launch_bounds__(256, 1) void out_gemm_tc(
    const float* __restrict__ Wo, const float* __restrict__ bo,
    const float* __restrict__ x, float* __restrict__ out) {
    __shared__ float As[GBK * LDK];
    __shared__ float Bs[GBK * LDK];
    const int row0 = blockIdx.y * GBM;
    const int col0 = blockIdx.x * GBN;

    float c[4][4][4];
    #pragma unroll
    for (int i = 0; i < 4; i++)
        #pragma unroll
        for (int j = 0; j < 4; j++)
            #pragma unroll
            for (int q = 0; q < 4; q++) c[i][j][q] = 0.f;

    gemm_tf32_mainloop(g_attn, Wo, row0, col0, c, As, Bs);

    const int lane = threadIdx.x & 31;
    const int warp = threadIdx.x >> 5;
    const int wr = warp >> 2, wc = warp & 3;
    const int lq = lane & 3, lg = lane >> 2;

    #pragma unroll
    for (int i = 0; i < 4; i++) {
        #pragma unroll
        for (int j = 0; j < 4; j++) {
            int cc = col0 + wc * 32 + j * 8 + 2 * lq;
            float b0 = bo[cc], b1 = bo[cc + 1];
            #pragma unroll
            for (int rh = 0; rh < 2; rh++) {
                int m = row0 + wr * 64 + i * 16 + lg + rh * 8;
                float2 xr = *(const float2*)&x[(size_t)m * DIM + cc];
                float2 r;
                r.x = c[i][j][rh * 2 + 0] + b0 + xr.x;
                r.y = c[i][j][rh * 2 + 1] + b1 + xr.y;
                *(float2*)&out[(size_t)m * DIM + cc] = r;
            }
        }
    }
}

// ---------------- flash-style attention (SIMT fp32, unchanged from R2) ----------------
#define ATTN_SMEM_FLOATS (64*65 + 64*68 + 64*65)
#define ATTN_SMEM_BYTES  (ATTN_SMEM_FLOATS * 4)

__global__ __launch_bounds__(256) void attn_kernel() {
    extern __shared__ float sm[];
    float* Qs = sm;                 // [64][65]
    float* KV = sm + 64 * 65;       // [64][68]
    float* Ss = KV + 64 * 68;       // [64][65]
    __shared__ float row_m[64], row_l[64], row_alpha[64];
    __shared__ float red[64][4];

    const int t  = threadIdx.x;
    const int tx = t & 15, ty = t >> 4;
    const int q0 = blockIdx.x * 64;
    const int bh = blockIdx.y;
    const float* Qg = g_Q + (size_t)bh * SEQ * HDIM;
    const float* Kg = g_K + (size_t)bh * SEQ * HDIM;
    const float* Vg = g_V + (size_t)bh * SEQ * HDIM;

    const int lr  = t >> 2;
    const int lc0 = (t & 3) * 16;

    {
        #pragma unroll
        for (int ii = 0; ii < 4; ii++) {
            int c = lc0 + ii * 4;
            float4 v = *(const float4*)&Qg[(size_t)(q0 + lr) * HDIM + c];
            Qs[lr * 65 + c + 0] = v.x; Qs[lr * 65 + c + 1] = v.y;
            Qs[lr * 65 + c + 2] = v.z; Qs[lr * 65 + c + 3] = v.w;
        }
    }
    if (t < 64) { row_m[t] = -1e30f; row_l[t] = 0.f; }

    float o[4][4];
    #pragma unroll
    for (int i = 0; i < 4; i++)
        #pragma unroll
        for (int j = 0; j < 4; j++) o[i][j] = 0.f;

    for (int n0 = 0; n0 < SEQ; n0 += 64) {
        {
            #pragma unroll
            for (int ii = 0; ii < 4; ii++) {
                int c = lc0 + ii * 4;
                float4 v = *(const float4*)&Kg[(size_t)(n0 + lr) * HDIM + c];
                KV[(c + 0) * 68 + lr] = v.x;
                KV[(c + 1) * 68 + lr] = v.y;
                KV[(c + 2) * 68 + lr] = v.z;
                KV[(c + 3) * 68 + lr] = v.w;
            }
        }
        __syncthreads();

        float s4[4][4];
        #pragma unroll
        for (int i = 0; i < 4; i++)
            #pragma unroll
            for (int j = 0; j < 4; j++) s4[i][j] = 0.f;
        #pragma unroll 8
        for (int kk = 0; kk < 64; kk++) {
            float a0 = Qs[(ty * 4 + 0) * 65 + kk];
            float a1 = Qs[(ty * 4 + 1) * 65 + kk];
            float a2 = Qs[(ty * 4 + 2) * 65 + kk];
            float a3 = Qs[(ty * 4 + 3) * 65 + kk];
            float4 b4 = *(const float4*)&KV[kk * 68 + tx * 4];
            s4[0][0] += a0 * b4.x; s4[0][1] += a0 * b4.y; s4[0][2] += a0 * b4.z; s4[0][3] += a0 * b4.w;
            s4[1][0] += a1 * b4.x; s4[1][1] += a1 * b4.y; s4[1][2] += a1 * b4.z; s4[1][3] += a1 * b4.w;
            s4[2][0] += a2 * b4.x; s4[2][1] += a2 * b4.y; s4[2][2] += a2 * b4.z; s4[2][3] += a2 * b4.w;
            s4[3][0] += a3 * b4.x; s4[3][1] += a3 * b4.y; s4[3][2] += a3 * b4.z; s4[3][3] += a3 * b4.w;
        }
        #pragma unroll
        for (int i = 0; i < 4; i++)
            #pragma unroll
            for (int j = 0; j < 4; j++)
                Ss[(ty * 4 + i) * 65 + tx * 4 + j] = s4[i][j] * 0.125f;
        __syncthreads();

        {
            float4 vload[4];
            #pragma unroll
            for (int ii = 0; ii < 4; ii++)
                vload[ii] = *(const float4*)&Vg[(size_t)(n0 + lr) * HDIM + lc0 + ii * 4];
            int r = t >> 2, q = t & 3;
            float pmax = -1e30f;
            #pragma unroll
            for (int cc = 0; cc < 16; cc++)
                pmax = fmaxf(pmax, Ss[r * 65 + q * 16 + cc]);
            #pragma unroll
            for (int ii = 0; ii < 4; ii++)
                *(float4*)&KV[lr * 68 + lc0 + ii * 4] = vload[ii];
            red[r][q] = pmax;
        }
        __syncthreads();

        if (t < 64) {
            float mx = fmaxf(fmaxf(red[t][0], red[t][1]), fmaxf(red[t][2], red[t][3]));
            float mold = row_m[t];
            float mnew = fmaxf(mold, mx);
            row_m[t] = mnew;
            row_alpha[t] = __expf(mold - mnew);
        }
        __syncthreads();

        {
            int r = t >> 2, q = t & 3;
            float mnew = row_m[r];
            float ps = 0.f;
            #pragma unroll
            for (int cc = 0; cc < 16; cc++) {
                int idx = r * 65 + q * 16 + cc;
                float e = __expf(Ss[idx] - mnew);
                Ss[idx] = e;
                ps += e;
            }
            red[r][q] = ps;
        }
        __syncthreads();

        if (t < 64)
            row_l[t] = row_l[t] * row_alpha[t] + (red[t][0] + red[t][1] + red[t][2] + red[t][3]);

        #pragma unroll
        for (int i = 0; i < 4; i++) {
            float al = row_alpha[ty * 4 + i];
            #pragma unroll
            for (int j = 0; j < 4; j++) o[i][j] *= al;
        }
        #pragma unroll 8
        for (int n = 0; n < 64; n++) {
            float4 v4 = *(const float4*)&KV[n * 68 + tx * 4];
            float p0 = Ss[(ty * 4 + 0) * 65 + n];
            float p1 = Ss[(ty * 4 + 1) * 65 + n];
            float p2 = Ss[(ty * 4 + 2) * 65 + n];
            float p3 = Ss[(ty * 4 + 3) * 65 + n];
            o[0][0] += p0 * v4.x; o[0][1] += p0 * v4.y; o[0][2] += p0 * v4.z; o[0][3] += p0 * v4.w;
            o[1][0] += p1 * v4.x; o[1][1] += p1 * v4.y; o[1][2] += p1 * v4.z; o[1][3] += p1 * v4.w;
            o[2][0] += p2 * v4.x; o[2][1] += p2 * v4.y; o[2][2] += p2 * v4.z; o[2][3] += p2 * v4.w;
            o[3][0] += p3 * v4.x; o[3][1] += p3 * v4.y; o[3][2] += p3 * v4.z; o[3][3] += p3 * v4.w;
        }
        __syncthreads();
    }

    const int b = bh / HEADS;
    const int h = bh % HEADS;
    #pragma unroll
    for (int i = 0; i < 4; i++) {
        int m = ty * 4 + i;
        float invl = 1.0f / row_l[m];
        float4 r;
        r.x = o[i][0] * invl; r.y = o[i][1] * invl;
        r.z = o[i][2] * invl; r.w = o[i][3] * invl;
        *(float4*)&g_attn[(size_t)(b * SEQ + q0 + m) * DIM + h * HDIM + tx * 4] = r;
    }
}

// ---------------- launcher ----------------
extern "C" void kernel_launch(void* const* d_in, const int* in_sizes, int n_in,
                              void* d_out, int out_size) {
    const float* x     = (const float*)d_in[0];
    const float* pos   = (const float*)d_in[1];
    const float* gamma = (const float*)d_in[2];
    const float* beta  = (const float*)d_in[3];
    const float* Wq    = (const float*)d_in[4];
    const float* bq    = (const float*)d_in[5];
    const float* Wk    = (const float*)d_in[6];
    const float* bk    = (const float*)d_in[7];
    const float* Wv    = (const float*)d_in[8];
    const float* bv    = (const float*)d_in[9];
    const float* Wo    = (const float*)d_in[10];
    const float* bo    = (const float*)d_in[11];
    float* out = (float*)d_out;

    cudaFuncSetAttribute(attn_kernel, cudaFuncAttributeMaxDynamicSharedMemorySize, 64 * 1024);

    ln_kernel<<<ROWS, 256>>>(x, gamma, beta);
    qkv_gemm_tc<<<dim3(DIM / GBN, ROWS / GBM, 3), 256>>>(Wq, bq, Wk, bk, Wv, bv, pos);
    attn_kernel<<<dim3(SEQ / 64, BATCH * HEADS), 256, ATTN_SMEM_BYTES>>>();
    out_gemm_tc<<<dim3(DIM / GBN, ROWS / GBM), 256>>>(Wo, bo, x, out);
}

// round 4
// speedup vs baseline: 1.8980x; 1.3949x over previous
#include <cuda_runtime.h>
#include <cstdint>

#define DIM   768
#define HEADS 12
#define HDIM  64
#define SEQ   1024
#define BATCH 8
#define ROWS  (BATCH*SEQ)   // 8192
#define LN_EPS 1e-5f

// ---------------- scratch ----------------
__device__ float g_xnorm[ROWS*DIM];
__device__ float g_Q[ROWS*DIM];      // (B,H,N,D)
__device__ float g_K[ROWS*DIM];      // (B,H,N,D)
__device__ float g_V[ROWS*DIM];      // (B,H,N,D)
__device__ float g_attn[ROWS*DIM];   // (B,N,C)

// ---------------- LayerNorm ----------------
__global__ __launch_bounds__(256) void ln_kernel(const float* __restrict__ x,
                                                 const float* __restrict__ gamma,
                                                 const float* __restrict__ beta) {
    int row = blockIdx.x;
    const float* xr = x + (size_t)row * DIM;
    float s = 0.f, sq = 0.f;
    for (int c = threadIdx.x; c < DIM; c += 256) { float v = xr[c]; s += v; sq += v * v; }
    #pragma unroll
    for (int o = 16; o > 0; o >>= 1) {
        s  += __shfl_xor_sync(0xffffffffu, s, o);
        sq += __shfl_xor_sync(0xffffffffu, sq, o);
    }
    __shared__ float ws[8], wsq[8];
    int w = threadIdx.x >> 5;
    if ((threadIdx.x & 31) == 0) { ws[w] = s; wsq[w] = sq; }
    __syncthreads();
    s = 0.f; sq = 0.f;
    #pragma unroll
    for (int i = 0; i < 8; i++) { s += ws[i]; sq += wsq[i]; }
    float mu  = s * (1.0f / DIM);
    float var = sq * (1.0f / DIM) - mu * mu;
    float inv = rsqrtf(var + LN_EPS);
    float* o = g_xnorm + (size_t)row * DIM;
    for (int c = threadIdx.x; c < DIM; c += 256)
        o[c] = (xr[c] - mu) * inv * gamma[c] + beta[c];
}

// ---------------- tf32 MMA macro ----------------
#define MMA_TF32(c, a, b) \
  asm volatile("mma.sync.aligned.m16n8k8.row.col.f32.tf32.tf32.f32 " \
    "{%0,%1,%2,%3}, {%4,%5,%6,%7}, {%8,%9}, {%0,%1,%2,%3};" \
    : "+f"((c)[0]), "+f"((c)[1]), "+f"((c)[2]), "+f"((c)[3]) \
    : "r"((a)[0]), "r"((a)[1]), "r"((a)[2]), "r"((a)[3]), "r"((b)[0]), "r"((b)[1]))

// ---------------- tf32 tensor-core projection GEMM ----------------
#define GBM 128
#define GBN 128
#define GBK 16
#define LDS_PAD 8
#define LDK (GBM + LDS_PAD)   // 136

__device__ __forceinline__ void gemm_tf32_mainloop(
    const float* __restrict__ A, const float* __restrict__ B,
    int row0, int col0, float c[4][4][4], float* As, float* Bs) {
    const int t    = threadIdx.x;
    const int lane = t & 31;
    const int warp = t >> 5;
    const int wr   = warp >> 2;
    const int wc   = warp & 3;
    const int lq   = lane & 3;
    const int lg   = lane >> 2;

    const int a_m = t >> 1;
    const int a_k = (t & 1) * 8;
    const int b_k = t >> 4;
    const int b_n = (t & 15) * 8;

    float4 pa0 = *(const float4*)&A[(size_t)(row0 + a_m) * DIM + a_k];
    float4 pa1 = *(const float4*)&A[(size_t)(row0 + a_m) * DIM + a_k + 4];
    float4 pb0 = *(const float4*)&B[(size_t)b_k * DIM + col0 + b_n];
    float4 pb1 = *(const float4*)&B[(size_t)b_k * DIM + col0 + b_n + 4];

    for (int k0 = 0; k0 < DIM; k0 += GBK) {
        As[(a_k + 0) * LDK + a_m] = pa0.x;
        As[(a_k + 1) * LDK + a_m] = pa0.y;
        As[(a_k + 2) * LDK + a_m] = pa0.z;
        As[(a_k + 3) * LDK + a_m] = pa0.w;
        As[(a_k + 4) * LDK + a_m] = pa1.x;
        As[(a_k + 5) * LDK + a_m] = pa1.y;
        As[(a_k + 6) * LDK + a_m] = pa1.z;
        As[(a_k + 7) * LDK + a_m] = pa1.w;
        *(float4*)&Bs[b_k * LDK + b_n]     = pb0;
        *(float4*)&Bs[b_k * LDK + b_n + 4] = pb1;
        __syncthreads();

        if (k0 + GBK < DIM) {
            pa0 = *(const float4*)&A[(size_t)(row0 + a_m) * DIM + k0 + GBK + a_k];
            pa1 = *(const float4*)&A[(size_t)(row0 + a_m) * DIM + k0 + GBK + a_k + 4];
            pb0 = *(const float4*)&B[(size_t)(k0 + GBK + b_k) * DIM + col0 + b_n];
            pb1 = *(const float4*)&B[(size_t)(k0 + GBK + b_k) * DIM + col0 + b_n + 4];
        }

        #pragma unroll
        for (int ks = 0; ks < 2; ks++) {
            const int kb = ks * 8;
            uint32_t af[4][4], bf[4][2];
            #pragma unroll
            for (int i = 0; i < 4; i++) {
                int m = wr * 64 + i * 16 + lg;
                af[i][0] = __float_as_uint(As[(kb + lq)     * LDK + m]);
                af[i][1] = __float_as_uint(As[(kb + lq)     * LDK + m + 8]);
                af[i][2] = __float_as_uint(As[(kb + lq + 4) * LDK + m]);
                af[i][3] = __float_as_uint(As[(kb + lq + 4) * LDK + m + 8]);
            }
            #pragma unroll
            for (int j = 0; j < 4; j++) {
                int n = wc * 32 + j * 8 + lg;
                bf[j][0] = __float_as_uint(Bs[(kb + lq)     * LDK + n]);
                bf[j][1] = __float_as_uint(Bs[(kb + lq + 4) * LDK + n]);
            }
            #pragma unroll
            for (int i = 0; i < 4; i++)
                #pragma unroll
                for (int j = 0; j < 4; j++)
                    MMA_TF32(c[i][j], af[i], bf[j]);
        }
        __syncthreads();
    }
}

__global__ __launch_bounds__(256, 1) void qkv_gemm_tc(
    const float* __restrict__ Wq, const float* __restrict__ bq,
    const float* __restrict__ Wk, const float* __restrict__ bk,
    const float* __restrict__ Wv, const float* __restrict__ bv,
    const float* __restrict__ pos) {
    __shared__ float As[GBK * LDK];
    __shared__ float Bs[GBK * LDK];
    const int which = blockIdx.z;
    const float* W    = (which == 0) ? Wq : ((which == 1) ? Wk : Wv);
    const float* bias = (which == 0) ? bq : ((which == 1) ? bk : bv);
    float* out        = (which == 0) ? g_Q : ((which == 1) ? g_K : g_V);

    const int row0 = blockIdx.y * GBM;
    const int col0 = blockIdx.x * GBN;

    float c[4][4][4];
    #pragma unroll
    for (int i = 0; i < 4; i++)
        #pragma unroll
        for (int j = 0; j < 4; j++)
            #pragma unroll
            for (int q = 0; q < 4; q++) c[i][j][q] = 0.f;

    gemm_tf32_mainloop(g_xnorm, W, row0, col0, c, As, Bs);

    const int lane = threadIdx.x & 31;
    const int warp = threadIdx.x >> 5;
    const int wr = warp >> 2, wc = warp & 3;
    const int lq = lane & 3, lg = lane >> 2;

    #pragma unroll
    for (int i = 0; i < 4; i++) {
        #pragma unroll
        for (int j = 0; j < 4; j++) {
            int cc = col0 + wc * 32 + j * 8 + 2 * lq;
            float b0 = bias[cc], b1 = bias[cc + 1];
            int h = cc >> 6, d = cc & 63;
            #pragma unroll
            for (int rh = 0; rh < 2; rh++) {
                int m = row0 + wr * 64 + i * 16 + lg + rh * 8;
                float v0 = c[i][j][rh * 2 + 0] + b0;
                float v1 = c[i][j][rh * 2 + 1] + b1;
                if (which == 0) {
                    float2 p = *(const float2*)&pos[(size_t)m * DIM + cc];
                    v0 += p.x; v1 += p.y;
                }
                int bidx = m >> 10, n = m & 1023;
                float2 r = make_float2(v0, v1);
                *(float2*)&out[(size_t)((bidx * HEADS + h) * SEQ + n) * HDIM + d] = r;
            }
        }
    }
}

__global__ __launch_bounds__(256, 1) void out_gemm_tc(
    const float* __restrict__ Wo, const float* __restrict__ bo,
    const float* __restrict__ x, float* __restrict__ out) {
    __shared__ float As[GBK * LDK];
    __shared__ float Bs[GBK * LDK];
    const int row0 = blockIdx.y * GBM;
    const int col0 = blockIdx.x * GBN;

    float c[4][4][4];
    #pragma unroll
    for (int i = 0; i < 4; i++)
        #pragma unroll
        for (int j = 0; j < 4; j++)
            #pragma unroll
            for (int q = 0; q < 4; q++) c[i][j][q] = 0.f;

    gemm_tf32_mainloop(g_attn, Wo, row0, col0, c, As, Bs);

    const int lane = threadIdx.x & 31;
    const int warp = threadIdx.x >> 5;
    const int wr = warp >> 2, wc = warp & 3;
    const int lq = lane & 3, lg = lane >> 2;

    #pragma unroll
    for (int i = 0; i < 4; i++) {
        #pragma unroll
        for (int j = 0; j < 4; j++) {
            int cc = col0 + wc * 32 + j * 8 + 2 * lq;
            float b0 = bo[cc], b1 = bo[cc + 1];
            #pragma unroll
            for (int rh = 0; rh < 2; rh++) {
                int m = row0 + wr * 64 + i * 16 + lg + rh * 8;
                float2 xr = *(const float2*)&x[(size_t)m * DIM + cc];
                float2 r;
                r.x = c[i][j][rh * 2 + 0] + b0 + xr.x;
                r.y = c[i][j][rh * 2 + 1] + b1 + xr.y;
                *(float2*)&out[(size_t)m * DIM + cc] = r;
            }
        }
    }
}

// ---------------- tensor-core flash attention ----------------
// 64-query tile per block, 8 warps in 2x4. Warp tile: 32 q x 16 keys (S) / 16 d (PV).
// Smem stride 68: A-fragment LDS pattern (4*lg+lq)%32 is conflict-free.
#define ALD 68
#define ATTN_SMEM_FLOATS (3 * 64 * ALD)
#define ATTN_SMEM_BYTES  (ATTN_SMEM_FLOATS * 4)

__global__ __launch_bounds__(256) void attn_tc_kernel() {
    extern __shared__ float sm[];
    float* Qs = sm;                 // [m][d]  64 x ALD
    float* KV = sm + 64 * ALD;      // K phase: [d][n]; V phase: [n][d]
    float* Ss = KV + 64 * ALD;      // [m][n]
    __shared__ float row_m[64], row_l[64], row_alpha[64];
    __shared__ float red[64][4];

    const int t    = threadIdx.x;
    const int lane = t & 31;
    const int warp = t >> 5;
    const int wr   = warp >> 2;      // 0..1 : query half
    const int wc   = warp & 3;       // 0..3 : key/d quarter
    const int lq   = lane & 3;
    const int lg   = lane >> 2;

    const int q0 = blockIdx.x * 64;
    const int bh = blockIdx.y;
    const float* Qg = g_Q + (size_t)bh * SEQ * HDIM;
    const float* Kg = g_K + (size_t)bh * SEQ * HDIM;
    const float* Vg = g_V + (size_t)bh * SEQ * HDIM;

    const int lr  = t >> 2;          // 0..63
    const int lc0 = (t & 3) * 16;    // 0,16,32,48

    // load Q tile [m][d]
    #pragma unroll
    for (int ii = 0; ii < 4; ii++) {
        int c = lc0 + ii * 4;
        *(float4*)&Qs[lr * ALD + c] = *(const float4*)&Qg[(size_t)(q0 + lr) * HDIM + c];
    }
    if (t < 64) { row_m[t] = -1e30f; row_l[t] = 0.f; }

    // persistent O accumulator: warp tile 32 q x 16 d -> 2 m-frags x 2 n-frags
    float o[2][2][4];
    #pragma unroll
    for (int i = 0; i < 2; i++)
        #pragma unroll
        for (int j = 0; j < 2; j++)
            #pragma unroll
            for (int q = 0; q < 4; q++) o[i][j][q] = 0.f;

    for (int n0 = 0; n0 < SEQ; n0 += 64) {
        // load K tile transposed: KV[d][n]
        #pragma unroll
        for (int ii = 0; ii < 4; ii++) {
            int c = lc0 + ii * 4;
            float4 v = *(const float4*)&Kg[(size_t)(n0 + lr) * HDIM + c];
            KV[(c + 0) * ALD + lr] = v.x;
            KV[(c + 1) * ALD + lr] = v.y;
            KV[(c + 2) * ALD + lr] = v.z;
            KV[(c + 3) * ALD + lr] = v.w;
        }
        __syncthreads();

        // S = Q @ K^T via MMA
        float c4[2][2][4];
        #pragma unroll
        for (int i = 0; i < 2; i++)
            #pragma unroll
            for (int j = 0; j < 2; j++)
                #pragma unroll
                for (int q = 0; q < 4; q++) c4[i][j][q] = 0.f;
        #pragma unroll
        for (int kb = 0; kb < 64; kb += 8) {
            uint32_t af[2][4], bf[2][2];
            #pragma unroll
            for (int i = 0; i < 2; i++) {
                int m = wr * 32 + i * 16 + lg;
                af[i][0] = __float_as_uint(Qs[m * ALD + kb + lq]);
                af[i][1] = __float_as_uint(Qs[(m + 8) * ALD + kb + lq]);
                af[i][2] = __float_as_uint(Qs[m * ALD + kb + lq + 4]);
                af[i][3] = __float_as_uint(Qs[(m + 8) * ALD + kb + lq + 4]);
            }
            #pragma unroll
            for (int j = 0; j < 2; j++) {
                int n = wc * 16 + j * 8 + lg;
                bf[j][0] = __float_as_uint(KV[(kb + lq) * ALD + n]);
                bf[j][1] = __float_as_uint(KV[(kb + lq + 4) * ALD + n]);
            }
            #pragma unroll
            for (int i = 0; i < 2; i++)
                #pragma unroll
                for (int j = 0; j < 2; j++)
                    MMA_TF32(c4[i][j], af[i], bf[j]);
        }
        // scale + write S to smem [m][n]
        #pragma unroll
        for (int i = 0; i < 2; i++) {
            #pragma unroll
            for (int j = 0; j < 2; j++) {
                int m = wr * 32 + i * 16 + lg;
                int n = wc * 16 + j * 8 + 2 * lq;
                Ss[m * ALD + n]     = c4[i][j][0] * 0.125f;
                Ss[m * ALD + n + 1] = c4[i][j][1] * 0.125f;
                Ss[(m + 8) * ALD + n]     = c4[i][j][2] * 0.125f;
                Ss[(m + 8) * ALD + n + 1] = c4[i][j][3] * 0.125f;
            }
        }
        __syncthreads();

        // phase A: V global load overlapped with partial row-max; V overwrites K
        {
            float4 vload[4];
            #pragma unroll
            for (int ii = 0; ii < 4; ii++)
                vload[ii] = *(const float4*)&Vg[(size_t)(n0 + lr) * HDIM + lc0 + ii * 4];
            int r = t >> 2, q = t & 3;
            float pmax = -1e30f;
            #pragma unroll
            for (int cc = 0; cc < 16; cc++)
                pmax = fmaxf(pmax, Ss[r * ALD + q * 16 + cc]);
            #pragma unroll
            for (int ii = 0; ii < 4; ii++)
                *(float4*)&KV[lr * ALD + lc0 + ii * 4] = vload[ii];  // V[n][d]
            red[r][q] = pmax;
        }
        __syncthreads();

        if (t < 64) {
            float mx = fmaxf(fmaxf(red[t][0], red[t][1]), fmaxf(red[t][2], red[t][3]));
            float mold = row_m[t];
            float mnew = fmaxf(mold, mx);
            row_m[t] = mnew;
            row_alpha[t] = __expf(mold - mnew);
        }
        __syncthreads();

        {   // exponentiate in place + partial sums
            int r = t >> 2, q = t & 3;
            float mnew = row_m[r];
            float ps = 0.f;
            #pragma unroll
            for (int cc = 0; cc < 16; cc++) {
                int idx = r * ALD + q * 16 + cc;
                float e = __expf(Ss[idx] - mnew);
                Ss[idx] = e;
                ps += e;
            }
            red[r][q] = ps;
        }
        __syncthreads();

        if (t < 64)
            row_l[t] = row_l[t] * row_alpha[t] + (red[t][0] + red[t][1] + red[t][2] + red[t][3]);
        __syncthreads();

        // rescale O by alpha (c-frag rows: lg and lg+8)
        #pragma unroll
        for (int i = 0; i < 2; i++) {
            float a0 = row_alpha[wr * 32 + i * 16 + lg];
            float a1 = row_alpha[wr * 32 + i * 16 + lg + 8];
            #pragma unroll
            for (int j = 0; j < 2; j++) {
                o[i][j][0] *= a0; o[i][j][1] *= a0;
                o[i][j][2] *= a1; o[i][j][3] *= a1;
            }
        }
        // O += P @ V via MMA (A = Ss[m][n], B = KV[n][d])
        #pragma unroll
        for (int kb = 0; kb < 64; kb += 8) {
            uint32_t af[2][4], bf[2][2];
            #pragma unroll
            for (int i = 0; i < 2; i++) {
                int m = wr * 32 + i * 16 + lg;
                af[i][0] = __float_as_uint(Ss[m * ALD + kb + lq]);
                af[i][1] = __float_as_uint(Ss[(m + 8) * ALD + kb + lq]);
                af[i][2] = __float_as_uint(Ss[m * ALD + kb + lq + 4]);
                af[i][3] = __float_as_uint(Ss[(m + 8) * ALD + kb + lq + 4]);
            }
            #pragma unroll
            for (int j = 0; j < 2; j++) {
                int d = wc * 16 + j * 8 + lg;
                bf[j][0] = __float_as_uint(KV[(kb + lq) * ALD + d]);
                bf[j][1] = __float_as_uint(KV[(kb + lq + 4) * ALD + d]);
            }
            #pragma unroll
            for (int i = 0; i < 2; i++)
                #pragma unroll
                for (int j = 0; j < 2; j++)
                    MMA_TF32(o[i][j], af[i], bf[j]);
        }
        __syncthreads();
    }

    // normalize + write back to (B,N,C)
    const int b = bh / HEADS;
    const int h = bh % HEADS;
    #pragma unroll
    for (int i = 0; i < 2; i++) {
        #pragma unroll
        for (int j = 0; j < 2; j++) {
            int d = wc * 16 + j * 8 + 2 * lq;
            #pragma unroll
            for (int rh = 0; rh < 2; rh++) {
                int mloc = wr * 32 + i * 16 + lg + rh * 8;
                float invl = 1.0f / row_l[mloc];
                float2 r;
                r.x = o[i][j][rh * 2 + 0] * invl;
                r.y = o[i][j][rh * 2 + 1] * invl;
                *(float2*)&g_attn[(size_t)(b * SEQ + q0 + mloc) * DIM + h * HDIM + d] = r;
            }
        }
    }
}

// ---------------- launcher ----------------
extern "C" void kernel_launch(void* const* d_in, const int* in_sizes, int n_in,
                              void* d_out, int out_size) {
    const float* x     = (const float*)d_in[0];
    const float* pos   = (const float*)d_in[1];
    const float* gamma = (const float*)d_in[2];
    const float* beta  = (const float*)d_in[3];
    const float* Wq    = (const float*)d_in[4];
    const float* bq    = (const float*)d_in[5];
    const float* Wk    = (const float*)d_in[6];
    const float* bk    = (const float*)d_in[7];
    const float* Wv    = (const float*)d_in[8];
    const float* bv    = (const float*)d_in[9];
    const float* Wo    = (const float*)d_in[10];
    const float* bo    = (const float*)d_in[11];
    float* out = (float*)d_out;

    cudaFuncSetAttribute(attn_tc_kernel, cudaFuncAttributeMaxDynamicSharedMemorySize, 64 * 1024);

    ln_kernel<<<ROWS, 256>>>(x, gamma, beta);
    qkv_gemm_tc<<<dim3(DIM / GBN, ROWS / GBM, 3), 256>>>(Wq, bq, Wk, bk, Wv, bv, pos);
    attn_tc_kernel<<<dim3(SEQ / 64, BATCH * HEADS), 256, ATTN_SMEM_BYTES>>>();
    out_gemm_tc<<<dim3(DIM / GBN, ROWS / GBM), 256>>>(Wo, bo, x, out);
}

// round 6
// speedup vs baseline: 2.0921x; 1.1022x over previous
#include <cuda_runtime.h>
#include <cstdint>

#define DIM   768
#define HEADS 12
#define HDIM  64
#define SEQ   1024
#define BATCH 8
#define ROWS  (BATCH*SEQ)   // 8192
#define LN_EPS 1e-5f

// ---------------- scratch ----------------
__device__ float g_xnorm[ROWS*DIM];
__device__ float g_Q[ROWS*DIM];      // (B,H,N,D)
__device__ float g_K[ROWS*DIM];      // (B,H,N,D)
__device__ float g_V[ROWS*DIM];      // (B,H,N,D)
__device__ float g_attn[ROWS*DIM];   // (B,N,C)

// ---------------- cp.async helpers ----------------
__device__ __forceinline__ void cp_async16(void* smem_ptr, const void* gptr) {
    uint32_t sa = (uint32_t)__cvta_generic_to_shared(smem_ptr);
    asm volatile("cp.async.cg.shared.global [%0], [%1], 16;" :: "r"(sa), "l"(gptr));
}
#define CP_COMMIT()  asm volatile("cp.async.commit_group;")
#define CP_WAIT(n)   asm volatile("cp.async.wait_group %0;" :: "n"(n))

// ---------------- LayerNorm: warp per row ----------------
__global__ __launch_bounds__(256) void ln_kernel(const float* __restrict__ x,
                                                 const float* __restrict__ gamma,
                                                 const float* __restrict__ beta) {
    int row  = blockIdx.x * 8 + (threadIdx.x >> 5);
    int lane = threadIdx.x & 31;
    const float* xr = x + (size_t)row * DIM;
    float4 v[6];
    float s = 0.f, sq = 0.f;
    #pragma unroll
    for (int i = 0; i < 6; i++) {
        v[i] = *(const float4*)&xr[(i * 32 + lane) * 4];
        s  += v[i].x + v[i].y + v[i].z + v[i].w;
        sq += v[i].x * v[i].x + v[i].y * v[i].y + v[i].z * v[i].z + v[i].w * v[i].w;
    }
    #pragma unroll
    for (int o = 16; o > 0; o >>= 1) {
        s  += __shfl_xor_sync(0xffffffffu, s, o);
        sq += __shfl_xor_sync(0xffffffffu, sq, o);
    }
    float mu  = s * (1.0f / DIM);
    float var = sq * (1.0f / DIM) - mu * mu;
    float inv = rsqrtf(var + LN_EPS);
    float* orow = g_xnorm + (size_t)row * DIM;
    #pragma unroll
    for (int i = 0; i < 6; i++) {
        int c = (i * 32 + lane) * 4;
        float4 g = *(const float4*)&gamma[c];
        float4 b = *(const float4*)&beta[c];
        float4 r;
        r.x = (v[i].x - mu) * inv * g.x + b.x;
        r.y = (v[i].y - mu) * inv * g.y + b.y;
        r.z = (v[i].z - mu) * inv * g.z + b.z;
        r.w = (v[i].w - mu) * inv * g.w + b.w;
        *(float4*)&orow[c] = r;
    }
}

// ---------------- tf32 MMA macro ----------------
#define MMA_TF32(c, a, b) \
  asm volatile("mma.sync.aligned.m16n8k8.row.col.f32.tf32.tf32.f32 " \
    "{%0,%1,%2,%3}, {%4,%5,%6,%7}, {%8,%9}, {%0,%1,%2,%3};" \
    : "+f"((c)[0]), "+f"((c)[1]), "+f"((c)[2]), "+f"((c)[3]) \
    : "r"((a)[0]), "r"((a)[1]), "r"((a)[2]), "r"((a)[3]), "r"((b)[0]), "r"((b)[1]))

// ---------------- tf32 GEMM: 4-stage cp.async pipeline ----------------
#define GBM 128
#define GBN 128
#define GBK 16
#define NST 4
#define LDA 20                 // As row stride (floats): (20*lg+lq)%32 conflict-free
#define LDB 136                // Bs row stride (floats): (8*lq+lg)%32 conflict-free
#define STAGE_F (GBM*LDA + GBK*LDB)   // 2560 + 2176 = 4736 floats per stage
#define GEMM_SMEM_BYTES (NST * STAGE_F * 4)
#define KT (DIM / GBK)         // 48

__device__ __forceinline__ void gemm_issue_stage(
    const float* __restrict__ A, const float* __restrict__ B,
    int row0, int col0, int k0, float* stage,
    int a_m, int a_k, int b_k, int b_n) {
    float* As = stage;
    float* Bs = stage + GBM * LDA;
    cp_async16(&As[a_m * LDA + a_k],     &A[(size_t)(row0 + a_m) * DIM + k0 + a_k]);
    cp_async16(&As[a_m * LDA + a_k + 4], &A[(size_t)(row0 + a_m) * DIM + k0 + a_k + 4]);
    cp_async16(&Bs[b_k * LDB + b_n],     &B[(size_t)(k0 + b_k) * DIM + col0 + b_n]);
    cp_async16(&Bs[b_k * LDB + b_n + 4], &B[(size_t)(k0 + b_k) * DIM + col0 + b_n + 4]);
}

__device__ __forceinline__ void gemm_tf32_mainloop(
    const float* __restrict__ A, const float* __restrict__ B,
    int row0, int col0, float c[4][4][4], float* dsm) {
    const int t    = threadIdx.x;
    const int lane = t & 31;
    const int warp = t >> 5;
    const int wr   = warp >> 2;
    const int wc   = warp & 3;
    const int lq   = lane & 3;
    const int lg   = lane >> 2;

    const int a_m = t >> 1;           // 0..127
    const int a_k = (t & 1) * 8;      // 0 or 8
    const int b_k = t >> 4;           // 0..15
    const int b_n = (t & 15) * 8;     // 0..120

    // prologue: fill NST-1 stages
    #pragma unroll
    for (int s = 0; s < NST - 1; s++) {
        gemm_issue_stage(A, B, row0, col0, s * GBK, dsm + s * STAGE_F, a_m, a_k, b_k, b_n);
        CP_COMMIT();
    }

    for (int kt = 0; kt < KT; kt++) {
        CP_WAIT(NST - 2);
        __syncthreads();

        // issue stage kt+NST-1 (into the slot consumed at iteration kt-1)
        if (kt + NST - 1 < KT) {
            gemm_issue_stage(A, B, row0, col0, (kt + NST - 1) * GBK,
                             dsm + ((kt + NST - 1) % NST) * STAGE_F, a_m, a_k, b_k, b_n);
        }
        CP_COMMIT();

        const float* As = dsm + (kt % NST) * STAGE_F;
        const float* Bs = As + GBM * LDA;

        #pragma unroll
        for (int ks = 0; ks < 2; ks++) {
            const int kb = ks * 8;
            uint32_t af[4][4], bf[4][2];
            #pragma unroll
            for (int i = 0; i < 4; i++) {
                int m = wr * 64 + i * 16 + lg;
                af[i][0] = __float_as_uint(As[m * LDA + kb + lq]);
                af[i][1] = __float_as_uint(As[(m + 8) * LDA + kb + lq]);
                af[i][2] = __float_as_uint(As[m * LDA + kb + lq + 4]);
                af[i][3] = __float_as_uint(As[(m + 8) * LDA + kb + lq + 4]);
            }
            #pragma unroll
            for (int j = 0; j < 4; j++) {
                int n = wc * 32 + j * 8 + lg;
                bf[j][0] = __float_as_uint(Bs[(kb + lq) * LDB + n]);
                bf[j][1] = __float_as_uint(Bs[(kb + lq + 4) * LDB + n]);
            }
            #pragma unroll
            for (int i = 0; i < 4; i++)
                #pragma unroll
                for (int j = 0; j < 4; j++)
                    MMA_TF32(c[i][j], af[i], bf[j]);
        }
    }
}

// QKV projection: out = xnorm @ W + b; z selects Q/K/V; Q adds pos. Output (B,H,N,D).
__global__ __launch_bounds__(256) void qkv_gemm_tc(
    const float* __restrict__ Wq, const float* __restrict__ bq,
    const float* __restrict__ Wk, const float* __restrict__ bk,
    const float* __restrict__ Wv, const float* __restrict__ bv,
    const float* __restrict__ pos) {
    extern __shared__ float dsm[];
    const int which = blockIdx.z;
    const float* W    = (which == 0) ? Wq : ((which == 1) ? Wk : Wv);
    const float* bias = (which == 0) ? bq : ((which == 1) ? bk : bv);
    float* out        = (which == 0) ? g_Q : ((which == 1) ? g_K : g_V);

    const int row0 = blockIdx.y * GBM;
    const int col0 = blockIdx.x * GBN;

    float c[4][4][4];
    #pragma unroll
    for (int i = 0; i < 4; i++)
        #pragma unroll
        for (int j = 0; j < 4; j++)
            #pragma unroll
            for (int q = 0; q < 4; q++) c[i][j][q] = 0.f;

    gemm_tf32_mainloop(g_xnorm, W, row0, col0, c, dsm);

    const int lane = threadIdx.x & 31;
    const int warp = threadIdx.x >> 5;
    const int wr = warp >> 2, wc = warp & 3;
    const int lq = lane & 3, lg = lane >> 2;

    #pragma unroll
    for (int i = 0; i < 4; i++) {
        #pragma unroll
        for (int j = 0; j < 4; j++) {
            int cc = col0 + wc * 32 + j * 8 + 2 * lq;
            float b0 = bias[cc], b1 = bias[cc + 1];
            int h = cc >> 6, d = cc & 63;
            #pragma unroll
            for (int rh = 0; rh < 2; rh++) {
                int m = row0 + wr * 64 + i * 16 + lg + rh * 8;
                float v0 = c[i][j][rh * 2 + 0] + b0;
                float v1 = c[i][j][rh * 2 + 1] + b1;
                if (which == 0) {
                    float2 p = *(const float2*)&pos[(size_t)m * DIM + cc];
                    v0 += p.x; v1 += p.y;
                }
                int bidx = m >> 10, n = m & 1023;
                float2 r = make_float2(v0, v1);
                *(float2*)&out[(size_t)((bidx * HEADS + h) * SEQ + n) * HDIM + d] = r;
            }
        }
    }
}

// Out projection + bias + residual: d_out = g_attn @ Wo + bo + x
__global__ __launch_bounds__(256) void out_gemm_tc(
    const float* __restrict__ Wo, const float* __restrict__ bo,
    const float* __restrict__ x, float* __restrict__ out) {
    extern __shared__ float dsm[];
    const int row0 = blockIdx.y * GBM;
    const int col0 = blockIdx.x * GBN;

    float c[4][4][4];
    #pragma unroll
    for (int i = 0; i < 4; i++)
        #pragma unroll
        for (int j = 0; j < 4; j++)
            #pragma unroll
            for (int q = 0; q < 4; q++) c[i][j][q] = 0.f;

    gemm_tf32_mainloop(g_attn, Wo, row0, col0, c, dsm);

    const int lane = threadIdx.x & 31;
    const int warp = threadIdx.x >> 5;
    const int wr = warp >> 2, wc = warp & 3;
    const int lq = lane & 3, lg = lane >> 2;

    #pragma unroll
    for (int i = 0; i < 4; i++) {
        #pragma unroll
        for (int j = 0; j < 4; j++) {
            int cc = col0 + wc * 32 + j * 8 + 2 * lq;
            float b0 = bo[cc], b1 = bo[cc + 1];
            #pragma unroll
            for (int rh = 0; rh < 2; rh++) {
                int m = row0 + wr * 64 + i * 16 + lg + rh * 8;
                float2 xr = *(const float2*)&x[(size_t)m * DIM + cc];
                float2 r;
                r.x = c[i][j][rh * 2 + 0] + b0 + xr.x;
                r.y = c[i][j][rh * 2 + 1] + b1 + xr.y;
                *(float2*)&out[(size_t)m * DIM + cc] = r;
            }
        }
    }
}

// ---------------- tensor-core flash attention ----------------
#define ALD 68
#define ATTN_SMEM_FLOATS (3 * 64 * ALD)
#define ATTN_SMEM_BYTES  (ATTN_SMEM_FLOATS * 4)

__global__ __launch_bounds__(256) void attn_tc_kernel() {
    extern __shared__ float sm[];
    float* Qs = sm;                 // [m][d]  64 x ALD
    float* KV = sm + 64 * ALD;      // K phase: [d][n]; V phase: [n][d]
    float* Ss = KV + 64 * ALD;      // [m][n]
    __shared__ float row_m[64], row_l[64], row_alpha[64];
    __shared__ float red[64][4];

    const int t    = threadIdx.x;
    const int lane = t & 31;
    const int warp = t >> 5;
    const int wr   = warp >> 2;
    const int wc   = warp & 3;
    const int lq   = lane & 3;
    const int lg   = lane >> 2;

    const int q0 = blockIdx.x * 64;
    const int bh = blockIdx.y;
    const float* Qg = g_Q + (size_t)bh * SEQ * HDIM;
    const float* Kg = g_K + (size_t)bh * SEQ * HDIM;
    const float* Vg = g_V + (size_t)bh * SEQ * HDIM;

    const int lr  = t >> 2;
    const int lc0 = (t & 3) * 16;

    #pragma unroll
    for (int ii = 0; ii < 4; ii++) {
        int c = lc0 + ii * 4;
        *(float4*)&Qs[lr * ALD + c] = *(const float4*)&Qg[(size_t)(q0 + lr) * HDIM + c];
    }
    if (t < 64) { row_m[t] = -1e30f; row_l[t] = 0.f; }

    float o[2][2][4];
    #pragma unroll
    for (int i = 0; i < 2; i++)
        #pragma unroll
        for (int j = 0; j < 2; j++)
            #pragma unroll
            for (int q = 0; q < 4; q++) o[i][j][q] = 0.f;

    for (int n0 = 0; n0 < SEQ; n0 += 64) {
        #pragma unroll
        for (int ii = 0; ii < 4; ii++) {
            int c = lc0 + ii * 4;
            float4 v = *(const float4*)&Kg[(size_t)(n0 + lr) * HDIM + c];
            KV[(c + 0) * ALD + lr] = v.x;
            KV[(c + 1) * ALD + lr] = v.y;
            KV[(c + 2) * ALD + lr] = v.z;
            KV[(c + 3) * ALD + lr] = v.w;
        }
        __syncthreads();

        float c4[2][2][4];
        #pragma unroll
        for (int i = 0; i < 2; i++)
            #pragma unroll
            for (int j = 0; j < 2; j++)
                #pragma unroll
                for (int q = 0; q < 4; q++) c4[i][j][q] = 0.f;
        #pragma unroll
        for (int kb = 0; kb < 64; kb += 8) {
            uint32_t af[2][4], bf[2][2];
            #pragma unroll
            for (int i = 0; i < 2; i++) {
                int m = wr * 32 + i * 16 + lg;
                af[i][0] = __float_as_uint(Qs[m * ALD + kb + lq]);
                af[i][1] = __float_as_uint(Qs[(m + 8) * ALD + kb + lq]);
                af[i][2] = __float_as_uint(Qs[m * ALD + kb + lq + 4]);
                af[i][3] = __float_as_uint(Qs[(m + 8) * ALD + kb + lq + 4]);
            }
            #pragma unroll
            for (int j = 0; j < 2; j++) {
                int n = wc * 16 + j * 8 + lg;
                bf[j][0] = __float_as_uint(KV[(kb + lq) * ALD + n]);
                bf[j][1] = __float_as_uint(KV[(kb + lq + 4) * ALD + n]);
            }
            #pragma unroll
            for (int i = 0; i < 2; i++)
                #pragma unroll
                for (int j = 0; j < 2; j++)
                    MMA_TF32(c4[i][j], af[i], bf[j]);
        }
        #pragma unroll
        for (int i = 0; i < 2; i++) {
            #pragma unroll
            for (int j = 0; j < 2; j++) {
                int m = wr * 32 + i * 16 + lg;
                int n = wc * 16 + j * 8 + 2 * lq;
                Ss[m * ALD + n]     = c4[i][j][0] * 0.125f;
                Ss[m * ALD + n + 1] = c4[i][j][1] * 0.125f;
                Ss[(m + 8) * ALD + n]     = c4[i][j][2] * 0.125f;
                Ss[(m + 8) * ALD + n + 1] = c4[i][j][3] * 0.125f;
            }
        }
        __syncthreads();

        {
            float4 vload[4];
            #pragma unroll
            for (int ii = 0; ii < 4; ii++)
                vload[ii] = *(const float4*)&Vg[(size_t)(n0 + lr) * HDIM + lc0 + ii * 4];
            int r = t >> 2, q = t & 3;
            float pmax = -1e30f;
            #pragma unroll
            for (int cc = 0; cc < 16; cc++)
                pmax = fmaxf(pmax, Ss[r * ALD + q * 16 + cc]);
            #pragma unroll
            for (int ii = 0; ii < 4; ii++)
                *(float4*)&KV[lr * ALD + lc0 + ii * 4] = vload[ii];
            red[r][q] = pmax;
        }
        __syncthreads();

        if (t < 64) {
            float mx = fmaxf(fmaxf(red[t][0], red[t][1]), fmaxf(red[t][2], red[t][3]));
            float mold = row_m[t];
            float mnew = fmaxf(mold, mx);
            row_m[t] = mnew;
            row_alpha[t] = __expf(mold - mnew);
        }
        __syncthreads();

        {
            int r = t >> 2, q = t & 3;
            float mnew = row_m[r];
            float ps = 0.f;
            #pragma unroll
            for (int cc = 0; cc < 16; cc++) {
                int idx = r * ALD + q * 16 + cc;
                float e = __expf(Ss[idx] - mnew);
                Ss[idx] = e;
                ps += e;
            }
            red[r][q] = ps;
        }
        __syncthreads();

        if (t < 64)
            row_l[t] = row_l[t] * row_alpha[t] + (red[t][0] + red[t][1] + red[t][2] + red[t][3]);
        __syncthreads();

        #pragma unroll
        for (int i = 0; i < 2; i++) {
            float a0 = row_alpha[wr * 32 + i * 16 + lg];
            float a1 = row_alpha[wr * 32 + i * 16 + lg + 8];
            #pragma unroll
            for (int j = 0; j < 2; j++) {
                o[i][j][0] *= a0; o[i][j][1] *= a0;
                o[i][j][2] *= a1; o[i][j][3] *= a1;
            }
        }
        #pragma unroll
        for (int kb = 0; kb < 64; kb += 8) {
            uint32_t af[2][4], bf[2][2];
            #pragma unroll
            for (int i = 0; i < 2; i++) {
                int m = wr * 32 + i * 16 + lg;
                af[i][0] = __float_as_uint(Ss[m * ALD + kb + lq]);
                af[i][1] = __float_as_uint(Ss[(m + 8) * ALD + kb + lq]);
                af[i][2] = __float_as_uint(Ss[m * ALD + kb + lq + 4]);
                af[i][3] = __float_as_uint(Ss[(m + 8) * ALD + kb + lq + 4]);
            }
            #pragma unroll
            for (int j = 0; j < 2; j++) {
                int d = wc * 16 + j * 8 + lg;
                bf[j][0] = __float_as_uint(KV[(kb + lq) * ALD + d]);
                bf[j][1] = __float_as_uint(KV[(kb + lq + 4) * ALD + d]);
            }
            #pragma unroll
            for (int i = 0; i < 2; i++)
                #pragma unroll
                for (int j = 0; j < 2; j++)
                    MMA_TF32(o[i][j], af[i], bf[j]);
        }
        __syncthreads();
    }

    const int b = bh / HEADS;
    const int h = bh % HEADS;
    #pragma unroll
    for (int i = 0; i < 2; i++) {
        #pragma unroll
        for (int j = 0; j < 2; j++) {
            int d = wc * 16 + j * 8 + 2 * lq;
            #pragma unroll
            for (int rh = 0; rh < 2; rh++) {
                int mloc = wr * 32 + i * 16 + lg + rh * 8;
                float invl = 1.0f / row_l[mloc];
                float2 r;
                r.x = o[i][j][rh * 2 + 0] * invl;
                r.y = o[i][j][rh * 2 + 1] * invl;
                *(float2*)&g_attn[(size_t)(b * SEQ + q0 + mloc) * DIM + h * HDIM + d] = r;
            }
        }
    }
}

// ---------------- launcher ----------------
extern "C" void kernel_launch(void* const* d_in, const int* in_sizes, int n_in,
                              void* d_out, int out_size) {
    const float* x     = (const float*)d_in[0];
    const float* pos   = (const float*)d_in[1];
    const float* gamma = (const float*)d_in[2];
    const float* beta  = (const float*)d_in[3];
    const float* Wq    = (const float*)d_in[4];
    const float* bq    = (const float*)d_in[5];
    const float* Wk    = (const float*)d_in[6];
    const float* bk    = (const float*)d_in[7];
    const float* Wv    = (const float*)d_in[8];
    const float* bv    = (const float*)d_in[9];
    const float* Wo    = (const float*)d_in[10];
    const float* bo    = (const float*)d_in[11];
    float* out = (float*)d_out;

    cudaFuncSetAttribute(attn_tc_kernel, cudaFuncAttributeMaxDynamicSharedMemorySize, 64 * 1024);
    cudaFuncSetAttribute(qkv_gemm_tc, cudaFuncAttributeMaxDynamicSharedMemorySize, GEMM_SMEM_BYTES);
    cudaFuncSetAttribute(out_gemm_tc, cudaFuncAttributeMaxDynamicSharedMemorySize, GEMM_SMEM_BYTES);

    ln_kernel<<<ROWS / 8, 256>>>(x, gamma, beta);
    qkv_gemm_tc<<<dim3(DIM / GBN, ROWS / GBM, 3), 256, GEMM_SMEM_BYTES>>>(Wq, bq, Wk, bk, Wv, bv, pos);
    attn_tc_kernel<<<dim3(SEQ / 64, BATCH * HEADS), 256, ATTN_SMEM_BYTES>>>();
    out_gemm_tc<<<dim3(DIM / GBN, ROWS / GBM), 256, GEMM_SMEM_BYTES>>>(Wo, bo, x, out);
}

// round 7
// speedup vs baseline: 5.0171x; 2.3981x over previous
#include <cuda_runtime.h>
#include <cuda_fp16.h>
#include <cstdint>

#define DIM   768
#define HEADS 12
#define HDIM  64
#define SEQ   1024
#define BATCH 8
#define ROWS  (BATCH*SEQ)   // 8192
#define NQKV  (3*DIM)       // 2304
#define LN_EPS 1e-5f

// ---------------- scratch (fp16 datapath) ----------------
__device__ __half g_xnorm[ROWS*DIM];
__device__ __half g_Q[ROWS*DIM];      // (B,H,N,D)
__device__ __half g_K[ROWS*DIM];
__device__ __half g_V[ROWS*DIM];
__device__ __half g_attn[ROWS*DIM];   // (B,N,C)
__device__ __half g_Wqkv[DIM*NQKV];   // [k][3*768] concat Q|K|V
__device__ __half g_Wo[DIM*DIM];      // [k][n]

// ---------------- helpers ----------------
__device__ __forceinline__ void cp_async16(void* smem_ptr, const void* gptr) {
    uint32_t sa = (uint32_t)__cvta_generic_to_shared(smem_ptr);
    asm volatile("cp.async.cg.shared.global [%0], [%1], 16;" :: "r"(sa), "l"(gptr));
}
#define CP_COMMIT()  asm volatile("cp.async.commit_group;")
#define CP_WAIT(n)   asm volatile("cp.async.wait_group %0;" :: "n"(n))

#define LDSM_X4(d0,d1,d2,d3,addr) \
  asm volatile("ldmatrix.sync.aligned.m8n8.x4.shared.b16 {%0,%1,%2,%3}, [%4];" \
    : "=r"(d0), "=r"(d1), "=r"(d2), "=r"(d3) : "r"(addr))
#define LDSM_X4T(d0,d1,d2,d3,addr) \
  asm volatile("ldmatrix.sync.aligned.m8n8.x4.trans.shared.b16 {%0,%1,%2,%3}, [%4];" \
    : "=r"(d0), "=r"(d1), "=r"(d2), "=r"(d3) : "r"(addr))

#define MMA_F16(c, a0,a1,a2,a3, b0,b1) \
  asm volatile("mma.sync.aligned.m16n8k16.row.col.f32.f16.f16.f32 " \
    "{%0,%1,%2,%3}, {%4,%5,%6,%7}, {%8,%9}, {%0,%1,%2,%3};" \
    : "+f"((c)[0]), "+f"((c)[1]), "+f"((c)[2]), "+f"((c)[3]) \
    : "r"(a0), "r"(a1), "r"(a2), "r"(a3), "r"(b0), "r"(b1))

// ---------------- weight conversion ----------------
__global__ __launch_bounds__(256) void convert_wqkv(const float* __restrict__ Wq,
                                                    const float* __restrict__ Wk,
                                                    const float* __restrict__ Wv) {
    int idx = (blockIdx.x * 256 + threadIdx.x) * 4;   // over 768*2304
    int k = idx / NQKV, ng = idx - k * NQKV;
    int which = ng / DIM, n = ng - which * DIM;
    const float* W = (which == 0) ? Wq : ((which == 1) ? Wk : Wv);
    float4 v = *(const float4*)&W[(size_t)k * DIM + n];
    __half* dst = &g_Wqkv[(size_t)k * NQKV + ng];
    *(half2*)dst       = __floats2half2_rn(v.x, v.y);
    *(half2*)(dst + 2) = __floats2half2_rn(v.z, v.w);
}
__global__ __launch_bounds__(256) void convert_wo(const float* __restrict__ Wo) {
    int idx = (blockIdx.x * 256 + threadIdx.x) * 4;   // over 768*768
    float4 v = *(const float4*)&Wo[idx];
    __half* dst = &g_Wo[idx];
    *(half2*)dst       = __floats2half2_rn(v.x, v.y);
    *(half2*)(dst + 2) = __floats2half2_rn(v.z, v.w);
}

// ---------------- LayerNorm: warp per row, fp16 out ----------------
__global__ __launch_bounds__(256) void ln_kernel(const float* __restrict__ x,
                                                 const float* __restrict__ gamma,
                                                 const float* __restrict__ beta) {
    int row  = blockIdx.x * 8 + (threadIdx.x >> 5);
    int lane = threadIdx.x & 31;
    const float* xr = x + (size_t)row * DIM;
    float4 v[6];
    float s = 0.f, sq = 0.f;
    #pragma unroll
    for (int i = 0; i < 6; i++) {
        v[i] = *(const float4*)&xr[(i * 32 + lane) * 4];
        s  += v[i].x + v[i].y + v[i].z + v[i].w;
        sq += v[i].x * v[i].x + v[i].y * v[i].y + v[i].z * v[i].z + v[i].w * v[i].w;
    }
    #pragma unroll
    for (int o = 16; o > 0; o >>= 1) {
        s  += __shfl_xor_sync(0xffffffffu, s, o);
        sq += __shfl_xor_sync(0xffffffffu, sq, o);
    }
    float mu  = s * (1.0f / DIM);
    float var = sq * (1.0f / DIM) - mu * mu;
    float inv = rsqrtf(var + LN_EPS);
    __half* orow = g_xnorm + (size_t)row * DIM;
    #pragma unroll
    for (int i = 0; i < 6; i++) {
        int c = (i * 32 + lane) * 4;
        float4 g = *(const float4*)&gamma[c];
        float4 b = *(const float4*)&beta[c];
        *(half2*)&orow[c]     = __floats2half2_rn((v[i].x - mu) * inv * g.x + b.x,
                                                  (v[i].y - mu) * inv * g.y + b.y);
        *(half2*)&orow[c + 2] = __floats2half2_rn((v[i].z - mu) * inv * g.z + b.z,
                                                  (v[i].w - mu) * inv * g.w + b.w);
    }
}

// ---------------- fp16 GEMM: 4-stage cp.async + ldmatrix ----------------
#define GBM 128
#define GBN 128
#define GBK 32
#define NST 4
#define LDA 40     // halfs; row = 80B -> ldmatrix rows conflict-free
#define LDB 136    // halfs; row = 272B
#define ASZ (GBM*LDA)            // 5120 halfs
#define BSZ (GBK*LDB)            // 4352 halfs
#define STAGE_H (ASZ + BSZ)      // 9472 halfs
#define GEMM_SMEM_BYTES (NST * STAGE_H * 2)   // 75776
#define KT (DIM / GBK)           // 24

__device__ __forceinline__ void gemm_issue_stage(
    const __half* __restrict__ A, const __half* __restrict__ B, int Bld,
    int row0, int col0, int k0, __half* stage,
    int a_m, int a_k0, int b_k, int b_n0) {
    __half* As = stage;
    __half* Bs = stage + ASZ;
    cp_async16(&As[a_m * LDA + a_k0],     &A[(size_t)(row0 + a_m) * DIM + k0 + a_k0]);
    cp_async16(&As[a_m * LDA + a_k0 + 8], &A[(size_t)(row0 + a_m) * DIM + k0 + a_k0 + 8]);
    cp_async16(&Bs[b_k * LDB + b_n0],     &B[(size_t)(k0 + b_k) * Bld + col0 + b_n0]);
    cp_async16(&Bs[b_k * LDB + b_n0 + 8], &B[(size_t)(k0 + b_k) * Bld + col0 + b_n0 + 8]);
}

__device__ __forceinline__ void gemm_f16_mainloop(
    const __half* __restrict__ A, const __half* __restrict__ B, int Bld,
    int row0, int col0, float c[4][4][4], __half* dsm) {
    const int t    = threadIdx.x;
    const int lane = t & 31;
    const int warp = t >> 5;
    const int wr   = warp >> 2;
    const int wc   = warp & 3;

    const int a_m  = t >> 1;
    const int a_k0 = (t & 1) * 16;
    const int b_k  = t >> 3;
    const int b_n0 = (t & 7) * 16;

    // ldmatrix lane offsets
    const int mrow = ((lane >> 3) & 1) * 8 + (lane & 7);  // A-pattern row
    const int mcol = (lane >> 4) * 8;                      // A-pattern col
    const uint32_t sbase = (uint32_t)__cvta_generic_to_shared(dsm);
    const uint32_t a_lds = sbase + (uint32_t)(((wr * 64 + mrow) * LDA + mcol) * 2);
    const uint32_t b_lds = sbase + (uint32_t)((ASZ + mrow * LDB + wc * 32 + mcol) * 2);

    #pragma unroll
    for (int s = 0; s < NST - 1; s++) {
        gemm_issue_stage(A, B, Bld, row0, col0, s * GBK, dsm + s * STAGE_H, a_m, a_k0, b_k, b_n0);
        CP_COMMIT();
    }

    for (int kt = 0; kt < KT; kt++) {
        CP_WAIT(NST - 2);
        __syncthreads();

        if (kt + NST - 1 < KT) {
            gemm_issue_stage(A, B, Bld, row0, col0, (kt + NST - 1) * GBK,
                             dsm + ((kt + NST - 1) % NST) * STAGE_H, a_m, a_k0, b_k, b_n0);
        }
        CP_COMMIT();

        const uint32_t stoff = (uint32_t)((kt % NST) * STAGE_H * 2);

        #pragma unroll
        for (int kb = 0; kb < GBK; kb += 16) {
            uint32_t af[4][4], bg[2][4];
            #pragma unroll
            for (int i = 0; i < 4; i++)
                LDSM_X4(af[i][0], af[i][1], af[i][2], af[i][3],
                        a_lds + stoff + (uint32_t)((i * 16 * LDA + kb) * 2));
            #pragma unroll
            for (int j2 = 0; j2 < 2; j2++)
                LDSM_X4T(bg[j2][0], bg[j2][1], bg[j2][2], bg[j2][3],
                         b_lds + stoff + (uint32_t)((kb * LDB + j2 * 16) * 2));
            #pragma unroll
            for (int i = 0; i < 4; i++)
                #pragma unroll
                for (int j = 0; j < 4; j++)
                    MMA_F16(c[i][j], af[i][0], af[i][1], af[i][2], af[i][3],
                            bg[j >> 1][(j & 1) * 2], bg[j >> 1][(j & 1) * 2 + 1]);
        }
    }
}

// Fused QKV projection over concatenated weights: one 8192x2304x768 GEMM.
__global__ __launch_bounds__(256) void qkv_gemm_f16(
    const float* __restrict__ bq, const float* __restrict__ bk,
    const float* __restrict__ bv, const float* __restrict__ pos) {
    extern __shared__ __half dsm[];
    const int row0 = blockIdx.y * GBM;
    const int col0 = blockIdx.x * GBN;

    float c[4][4][4];
    #pragma unroll
    for (int i = 0; i < 4; i++)
        #pragma unroll
        for (int j = 0; j < 4; j++)
            #pragma unroll
            for (int q = 0; q < 4; q++) c[i][j][q] = 0.f;

    gemm_f16_mainloop(g_xnorm, g_Wqkv, NQKV, row0, col0, c, dsm);

    const int lane = threadIdx.x & 31;
    const int warp = threadIdx.x >> 5;
    const int wr = warp >> 2, wc = warp & 3;
    const int lq = lane & 3, lg = lane >> 2;

    const int which = col0 / DIM;   // 768 % 128 == 0 -> uniform per block
    const float* bias = (which == 0) ? bq : ((which == 1) ? bk : bv);
    __half* out = (which == 0) ? g_Q : ((which == 1) ? g_K : g_V);

    #pragma unroll
    for (int i = 0; i < 4; i++) {
        #pragma unroll
        for (int j = 0; j < 4; j++) {
            int cg = col0 + wc * 32 + j * 8 + 2 * lq;
            int nl = cg - which * DIM;           // 0..767
            float b0 = bias[nl], b1 = bias[nl + 1];
            int h = nl >> 6, d = nl & 63;
            #pragma unroll
            for (int rh = 0; rh < 2; rh++) {
                int m = row0 + wr * 64 + i * 16 + lg + rh * 8;
                float v0 = c[i][j][rh * 2 + 0] + b0;
                float v1 = c[i][j][rh * 2 + 1] + b1;
                if (which == 0) {
                    float2 p = *(const float2*)&pos[(size_t)m * DIM + nl];
                    v0 += p.x; v1 += p.y;
                }
                int bidx = m >> 10, n = m & 1023;
                *(half2*)&out[(size_t)((bidx * HEADS + h) * SEQ + n) * HDIM + d] =
                    __floats2half2_rn(v0, v1);
            }
        }
    }
}

// Out projection + bias + residual: d_out = g_attn @ Wo + bo + x  (fp32 out)
__global__ __launch_bounds__(256) void out_gemm_f16(
    const float* __restrict__ bo, const float* __restrict__ x, float* __restrict__ out) {
    extern __shared__ __half dsm[];
    const int row0 = blockIdx.y * GBM;
    const int col0 = blockIdx.x * GBN;

    float c[4][4][4];
    #pragma unroll
    for (int i = 0; i < 4; i++)
        #pragma unroll
        for (int j = 0; j < 4; j++)
            #pragma unroll
            for (int q = 0; q < 4; q++) c[i][j][q] = 0.f;

    gemm_f16_mainloop(g_attn, g_Wo, DIM, row0, col0, c, dsm);

    const int lane = threadIdx.x & 31;
    const int warp = threadIdx.x >> 5;
    const int wr = warp >> 2, wc = warp & 3;
    const int lq = lane & 3, lg = lane >> 2;

    #pragma unroll
    for (int i = 0; i < 4; i++) {
        #pragma unroll
        for (int j = 0; j < 4; j++) {
            int cc = col0 + wc * 32 + j * 8 + 2 * lq;
            float b0 = bo[cc], b1 = bo[cc + 1];
            #pragma unroll
            for (int rh = 0; rh < 2; rh++) {
                int m = row0 + wr * 64 + i * 16 + lg + rh * 8;
                float2 xr = *(const float2*)&x[(size_t)m * DIM + cc];
                float2 r;
                r.x = c[i][j][rh * 2 + 0] + b0 + xr.x;
                r.y = c[i][j][rh * 2 + 1] + b1 + xr.y;
                *(float2*)&out[(size_t)m * DIM + cc] = r;
            }
        }
    }
}

// ---------------- fp16 tensor-core flash attention ----------------
#define LDH 72   // halfs; row = 144B -> ldmatrix rows conflict-free

__global__ __launch_bounds__(256) void attn_f16_kernel() {
    __shared__ __align__(16) __half Qs[64 * LDH];
    __shared__ __align__(16) __half Ks[64 * LDH];
    __shared__ __align__(16) __half Vs[64 * LDH];
    __shared__ __align__(16) __half Ss[64 * LDH];
    __shared__ float row_m[64], row_l[64], row_alpha[64];
    __shared__ float red[64][4];

    const int t    = threadIdx.x;
    const int lane = t & 31;
    const int warp = t >> 5;
    const int wr   = warp >> 2;     // query half (32 rows)
    const int wc   = warp & 3;      // key/d quarter (16)
    const int lq   = lane & 3;
    const int lg   = lane >> 2;

    const int q0 = blockIdx.x * 64;
    const int bh = blockIdx.y;
    const __half* Qg = g_Q + (size_t)bh * SEQ * HDIM;
    const __half* Kg = g_K + (size_t)bh * SEQ * HDIM;
    const __half* Vg = g_V + (size_t)bh * SEQ * HDIM;

    const int lr  = t >> 2;         // 0..63
    const int lc0 = (t & 3) * 16;   // 0,16,32,48

    // ldmatrix lane offsets
    const int mrow = ((lane >> 3) & 1) * 8 + (lane & 7);   // A/V pattern
    const int mcol = (lane >> 4) * 8;
    const int nrow = (lane >> 4) * 8 + (lane & 7);         // K(B) pattern
    const int kcol = ((lane >> 3) & 1) * 8;

    const uint32_t qs_u = (uint32_t)__cvta_generic_to_shared(Qs);
    const uint32_t ks_u = (uint32_t)__cvta_generic_to_shared(Ks);
    const uint32_t vs_u = (uint32_t)__cvta_generic_to_shared(Vs);
    const uint32_t ss_u = (uint32_t)__cvta_generic_to_shared(Ss);
    const uint32_t a_off = (uint32_t)(((wr * 32 + mrow) * LDH + mcol) * 2);
    const uint32_t kb_off = (uint32_t)(((wc * 16 + nrow) * LDH + kcol) * 2);
    const uint32_t vb_off = (uint32_t)((mrow * LDH + wc * 16 + mcol) * 2);

    // load Q tile [m][d]
    *(uint4*)&Qs[lr * LDH + lc0]     = *(const uint4*)&Qg[(size_t)(q0 + lr) * HDIM + lc0];
    *(uint4*)&Qs[lr * LDH + lc0 + 8] = *(const uint4*)&Qg[(size_t)(q0 + lr) * HDIM + lc0 + 8];
    if (t < 64) { row_m[t] = -1e30f; row_l[t] = 0.f; }

    float o[2][2][4];
    #pragma unroll
    for (int i = 0; i < 2; i++)
        #pragma unroll
        for (int j = 0; j < 2; j++)
            #pragma unroll
            for (int q = 0; q < 4; q++) o[i][j][q] = 0.f;

    for (int n0 = 0; n0 < SEQ; n0 += 64) {
        // load K,V tiles [n][d]
        *(uint4*)&Ks[lr * LDH + lc0]     = *(const uint4*)&Kg[(size_t)(n0 + lr) * HDIM + lc0];
        *(uint4*)&Ks[lr * LDH + lc0 + 8] = *(const uint4*)&Kg[(size_t)(n0 + lr) * HDIM + lc0 + 8];
        *(uint4*)&Vs[lr * LDH + lc0]     = *(const uint4*)&Vg[(size_t)(n0 + lr) * HDIM + lc0];
        *(uint4*)&Vs[lr * LDH + lc0 + 8] = *(const uint4*)&Vg[(size_t)(n0 + lr) * HDIM + lc0 + 8];
        __syncthreads();

        // S = Q @ K^T
        float c4[2][2][4];
        #pragma unroll
        for (int i = 0; i < 2; i++)
            #pragma unroll
            for (int j = 0; j < 2; j++)
                #pragma unroll
                for (int q = 0; q < 4; q++) c4[i][j][q] = 0.f;
        #pragma unroll
        for (int kb = 0; kb < 64; kb += 16) {
            uint32_t af[2][4], bf[4];
            #pragma unroll
            for (int i = 0; i < 2; i++)
                LDSM_X4(af[i][0], af[i][1], af[i][2], af[i][3],
                        qs_u + a_off + (uint32_t)((i * 16 * LDH + kb) * 2));
            LDSM_X4(bf[0], bf[1], bf[2], bf[3], ks_u + kb_off + (uint32_t)(kb * 2));
            #pragma unroll
            for (int i = 0; i < 2; i++) {
                MMA_F16(c4[i][0], af[i][0], af[i][1], af[i][2], af[i][3], bf[0], bf[1]);
                MMA_F16(c4[i][1], af[i][0], af[i][1], af[i][2], af[i][3], bf[2], bf[3]);
            }
        }
        #pragma unroll
        for (int i = 0; i < 2; i++)
            #pragma unroll
            for (int j = 0; j < 2; j++)
                #pragma unroll
                for (int q = 0; q < 4; q++) c4[i][j][q] *= 0.125f;

        // partial row max (per-thread 4 cols) -> shuffle over lq -> red[row][wc]
        float pm[2][2];
        #pragma unroll
        for (int i = 0; i < 2; i++) {
            pm[i][0] = fmaxf(fmaxf(c4[i][0][0], c4[i][0][1]), fmaxf(c4[i][1][0], c4[i][1][1]));
            pm[i][1] = fmaxf(fmaxf(c4[i][0][2], c4[i][0][3]), fmaxf(c4[i][1][2], c4[i][1][3]));
            #pragma unroll
            for (int rh = 0; rh < 2; rh++) {
                pm[i][rh] = fmaxf(pm[i][rh], __shfl_xor_sync(0xffffffffu, pm[i][rh], 1));
                pm[i][rh] = fmaxf(pm[i][rh], __shfl_xor_sync(0xffffffffu, pm[i][rh], 2));
            }
        }
        if (lq == 0) {
            #pragma unroll
            for (int i = 0; i < 2; i++) {
                red[wr * 32 + i * 16 + lg][wc]     = pm[i][0];
                red[wr * 32 + i * 16 + lg + 8][wc] = pm[i][1];
            }
        }
        __syncthreads();

        if (t < 64) {
            float mx = fmaxf(fmaxf(red[t][0], red[t][1]), fmaxf(red[t][2], red[t][3]));
            float mold = row_m[t];
            float mnew = fmaxf(mold, mx);
            row_m[t] = mnew;
            row_alpha[t] = __expf(mold - mnew);
        }
        __syncthreads();

        // exp -> store P to Ss as fp16, accumulate partial sums
        float ps[2][2] = {{0.f, 0.f}, {0.f, 0.f}};
        #pragma unroll
        for (int i = 0; i < 2; i++) {
            int r0 = wr * 32 + i * 16 + lg;
            float m0 = row_m[r0], m1 = row_m[r0 + 8];
            #pragma unroll
            for (int j = 0; j < 2; j++) {
                int ncol = wc * 16 + j * 8 + 2 * lq;
                float e0 = __expf(c4[i][j][0] - m0);
                float e1 = __expf(c4[i][j][1] - m0);
                float e2 = __expf(c4[i][j][2] - m1);
                float e3 = __expf(c4[i][j][3] - m1);
                ps[i][0] += e0 + e1;
                ps[i][1] += e2 + e3;
                *(half2*)&Ss[r0 * LDH + ncol]       = __floats2half2_rn(e0, e1);
                *(half2*)&Ss[(r0 + 8) * LDH + ncol] = __floats2half2_rn(e2, e3);
            }
            #pragma unroll
            for (int rh = 0; rh < 2; rh++) {
                ps[i][rh] += __shfl_xor_sync(0xffffffffu, ps[i][rh], 1);
                ps[i][rh] += __shfl_xor_sync(0xffffffffu, ps[i][rh], 2);
            }
        }
        if (lq == 0) {
            #pragma unroll
            for (int i = 0; i < 2; i++) {
                red[wr * 32 + i * 16 + lg][wc]     = ps[i][0];
                red[wr * 32 + i * 16 + lg + 8][wc] = ps[i][1];
            }
        }
        __syncthreads();

        if (t < 64)
            row_l[t] = row_l[t] * row_alpha[t] + (red[t][0] + red[t][1] + red[t][2] + red[t][3]);

        // rescale O by alpha
        #pragma unroll
        for (int i = 0; i < 2; i++) {
            float a0 = row_alpha[wr * 32 + i * 16 + lg];
            float a1 = row_alpha[wr * 32 + i * 16 + lg + 8];
            #pragma unroll
            for (int j = 0; j < 2; j++) {
                o[i][j][0] *= a0; o[i][j][1] *= a0;
                o[i][j][2] *= a1; o[i][j][3] *= a1;
            }
        }
        // O += P @ V  (A=Ss[m][n], B=Vs[n][d] via ldmatrix trans)
        #pragma unroll
        for (int kb = 0; kb < 64; kb += 16) {
            uint32_t af[2][4], bf[4];
            #pragma unroll
            for (int i = 0; i < 2; i++)
                LDSM_X4(af[i][0], af[i][1], af[i][2], af[i][3],
                        ss_u + a_off + (uint32_t)((i * 16 * LDH + kb) * 2));
            LDSM_X4T(bf[0], bf[1], bf[2], bf[3], vs_u + vb_off + (uint32_t)(kb * LDH * 2));
            #pragma unroll
            for (int i = 0; i < 2; i++) {
                MMA_F16(o[i][0], af[i][0], af[i][1], af[i][2], af[i][3], bf[0], bf[1]);
                MMA_F16(o[i][1], af[i][0], af[i][1], af[i][2], af[i][3], bf[2], bf[3]);
            }
        }
        __syncthreads();
    }
    __syncthreads();

    // normalize + write to (B,N,C) as fp16
    const int b = bh / HEADS;
    const int h = bh % HEADS;
    #pragma unroll
    for (int i = 0; i < 2; i++) {
        #pragma unroll
        for (int j = 0; j < 2; j++) {
            int d = wc * 16 + j * 8 + 2 * lq;
            #pragma unroll
            for (int rh = 0; rh < 2; rh++) {
                int mloc = wr * 32 + i * 16 + lg + rh * 8;
                float invl = 1.0f / row_l[mloc];
                *(half2*)&g_attn[(size_t)(b * SEQ + q0 + mloc) * DIM + h * HDIM + d] =
                    __floats2half2_rn(o[i][j][rh * 2 + 0] * invl,
                                      o[i][j][rh * 2 + 1] * invl);
            }
        }
    }
}

// ---------------- launcher ----------------
extern "C" void kernel_launch(void* const* d_in, const int* in_sizes, int n_in,
                              void* d_out, int out_size) {
    const float* x     = (const float*)d_in[0];
    const float* pos   = (const float*)d_in[1];
    const float* gamma = (const float*)d_in[2];
    const float* beta  = (const float*)d_in[3];
    const float* Wq    = (const float*)d_in[4];
    const float* bq    = (const float*)d_in[5];
    const float* Wk    = (const float*)d_in[6];
    const float* bk    = (const float*)d_in[7];
    const float* Wv    = (const float*)d_in[8];
    const float* bv    = (const float*)d_in[9];
    const float* Wo    = (const float*)d_in[10];
    const float* bo    = (const float*)d_in[11];
    float* out = (float*)d_out;

    cudaFuncSetAttribute(qkv_gemm_f16, cudaFuncAttributeMaxDynamicSharedMemorySize, GEMM_SMEM_BYTES);
    cudaFuncSetAttribute(out_gemm_f16, cudaFuncAttributeMaxDynamicSharedMemorySize, GEMM_SMEM_BYTES);

    convert_wqkv<<<DIM * NQKV / 1024, 256>>>(Wq, Wk, Wv);
    convert_wo<<<DIM * DIM / 1024, 256>>>(Wo);
    ln_kernel<<<ROWS / 8, 256>>>(x, gamma, beta);
    qkv_gemm_f16<<<dim3(NQKV / GBN, ROWS / GBM), 256, GEMM_SMEM_BYTES>>>(bq, bk, bv, pos);
    attn_f16_kernel<<<dim3(SEQ / 64, BATCH * HEADS), 256>>>();
    out_gemm_f16<<<dim3(DIM / GBN, ROWS / GBM), 256, GEMM_SMEM_BYTES>>>(bo, x, out);
}

// round 8
// speedup vs baseline: 5.6896x; 1.1340x over previous
#include <cuda_runtime.h>
#include <cuda_fp16.h>
#include <cstdint>

#define DIM   768
#define HEADS 12
#define HDIM  64
#define SEQ   1024
#define BATCH 8
#define ROWS  (BATCH*SEQ)   // 8192
#define NQKV  (3*DIM)       // 2304
#define LN_EPS 1e-5f

// ---------------- scratch (fp16 datapath) ----------------
__device__ __half g_xnorm[ROWS*DIM];
__device__ __half g_Q[ROWS*DIM];      // (B,H,N,D)
__device__ __half g_K[ROWS*DIM];
__device__ __half g_V[ROWS*DIM];
__device__ __half g_attn[ROWS*DIM];   // (B,N,C)
__device__ __half g_Wqkv[DIM*NQKV];   // [k][3*768] concat Q|K|V
__device__ __half g_Wo[DIM*DIM];      // [k][n]

// ---------------- helpers ----------------
__device__ __forceinline__ void cp_async16(void* smem_ptr, const void* gptr) {
    uint32_t sa = (uint32_t)__cvta_generic_to_shared(smem_ptr);
    asm volatile("cp.async.cg.shared.global [%0], [%1], 16;" :: "r"(sa), "l"(gptr));
}
#define CP_COMMIT()  asm volatile("cp.async.commit_group;")
#define CP_WAIT(n)   asm volatile("cp.async.wait_group %0;" :: "n"(n))

#define LDSM_X4(d0,d1,d2,d3,addr) \
  asm volatile("ldmatrix.sync.aligned.m8n8.x4.shared.b16 {%0,%1,%2,%3}, [%4];" \
    : "=r"(d0), "=r"(d1), "=r"(d2), "=r"(d3) : "r"(addr))
#define LDSM_X4T(d0,d1,d2,d3,addr) \
  asm volatile("ldmatrix.sync.aligned.m8n8.x4.trans.shared.b16 {%0,%1,%2,%3}, [%4];" \
    : "=r"(d0), "=r"(d1), "=r"(d2), "=r"(d3) : "r"(addr))

#define MMA_F16(c, a0,a1,a2,a3, b0,b1) \
  asm volatile("mma.sync.aligned.m16n8k16.row.col.f32.f16.f16.f32 " \
    "{%0,%1,%2,%3}, {%4,%5,%6,%7}, {%8,%9}, {%0,%1,%2,%3};" \
    : "+f"((c)[0]), "+f"((c)[1]), "+f"((c)[2]), "+f"((c)[3]) \
    : "r"(a0), "r"(a1), "r"(a2), "r"(a3), "r"(b0), "r"(b1))

// ---------------- weight conversion ----------------
__global__ __launch_bounds__(256) void convert_wqkv(const float* __restrict__ Wq,
                                                    const float* __restrict__ Wk,
                                                    const float* __restrict__ Wv) {
    int idx = (blockIdx.x * 256 + threadIdx.x) * 4;
    int k = idx / NQKV, ng = idx - k * NQKV;
    int which = ng / DIM, n = ng - which * DIM;
    const float* W = (which == 0) ? Wq : ((which == 1) ? Wk : Wv);
    float4 v = *(const float4*)&W[(size_t)k * DIM + n];
    __half* dst = &g_Wqkv[(size_t)k * NQKV + ng];
    *(half2*)dst       = __floats2half2_rn(v.x, v.y);
    *(half2*)(dst + 2) = __floats2half2_rn(v.z, v.w);
}
__global__ __launch_bounds__(256) void convert_wo(const float* __restrict__ Wo) {
    int idx = (blockIdx.x * 256 + threadIdx.x) * 4;
    float4 v = *(const float4*)&Wo[idx];
    __half* dst = &g_Wo[idx];
    *(half2*)dst       = __floats2half2_rn(v.x, v.y);
    *(half2*)(dst + 2) = __floats2half2_rn(v.z, v.w);
}

// ---------------- LayerNorm: warp per row, fp16 out ----------------
__global__ __launch_bounds__(256) void ln_kernel(const float* __restrict__ x,
                                                 const float* __restrict__ gamma,
                                                 const float* __restrict__ beta) {
    int row  = blockIdx.x * 8 + (threadIdx.x >> 5);
    int lane = threadIdx.x & 31;
    const float* xr = x + (size_t)row * DIM;
    float4 v[6];
    float s = 0.f, sq = 0.f;
    #pragma unroll
    for (int i = 0; i < 6; i++) {
        v[i] = *(const float4*)&xr[(i * 32 + lane) * 4];
        s  += v[i].x + v[i].y + v[i].z + v[i].w;
        sq += v[i].x * v[i].x + v[i].y * v[i].y + v[i].z * v[i].z + v[i].w * v[i].w;
    }
    #pragma unroll
    for (int o = 16; o > 0; o >>= 1) {
        s  += __shfl_xor_sync(0xffffffffu, s, o);
        sq += __shfl_xor_sync(0xffffffffu, sq, o);
    }
    float mu  = s * (1.0f / DIM);
    float var = sq * (1.0f / DIM) - mu * mu;
    float inv = rsqrtf(var + LN_EPS);
    __half* orow = g_xnorm + (size_t)row * DIM;
    #pragma unroll
    for (int i = 0; i < 6; i++) {
        int c = (i * 32 + lane) * 4;
        float4 g = *(const float4*)&gamma[c];
        float4 b = *(const float4*)&beta[c];
        *(half2*)&orow[c]     = __floats2half2_rn((v[i].x - mu) * inv * g.x + b.x,
                                                  (v[i].y - mu) * inv * g.y + b.y);
        *(half2*)&orow[c + 2] = __floats2half2_rn((v[i].z - mu) * inv * g.z + b.z,
                                                  (v[i].w - mu) * inv * g.w + b.w);
    }
}

// ---------------- fp16 GEMM: 4-stage cp.async + ldmatrix (unchanged from R7) ----------------
#define GBM 128
#define GBN 128
#define GBK 32
#define NST 4
#define LDA 40
#define LDB 136
#define ASZ (GBM*LDA)
#define BSZ (GBK*LDB)
#define STAGE_H (ASZ + BSZ)
#define GEMM_SMEM_BYTES (NST * STAGE_H * 2)
#define KT (DIM / GBK)

__device__ __forceinline__ void gemm_issue_stage(
    const __half* __restrict__ A, const __half* __restrict__ B, int Bld,
    int row0, int col0, int k0, __half* stage,
    int a_m, int a_k0, int b_k, int b_n0) {
    __half* As = stage;
    __half* Bs = stage + ASZ;
    cp_async16(&As[a_m * LDA + a_k0],     &A[(size_t)(row0 + a_m) * DIM + k0 + a_k0]);
    cp_async16(&As[a_m * LDA + a_k0 + 8], &A[(size_t)(row0 + a_m) * DIM + k0 + a_k0 + 8]);
    cp_async16(&Bs[b_k * LDB + b_n0],     &B[(size_t)(k0 + b_k) * Bld + col0 + b_n0]);
    cp_async16(&Bs[b_k * LDB + b_n0 + 8], &B[(size_t)(k0 + b_k) * Bld + col0 + b_n0 + 8]);
}

__device__ __forceinline__ void gemm_f16_mainloop(
    const __half* __restrict__ A, const __half* __restrict__ B, int Bld,
    int row0, int col0, float c[4][4][4], __half* dsm) {
    const int t    = threadIdx.x;
    const int lane = t & 31;
    const int warp = t >> 5;
    const int wr   = warp >> 2;
    const int wc   = warp & 3;

    const int a_m  = t >> 1;
    const int a_k0 = (t & 1) * 16;
    const int b_k  = t >> 3;
    const int b_n0 = (t & 7) * 16;

    const int mrow = ((lane >> 3) & 1) * 8 + (lane & 7);
    const int mcol = (lane >> 4) * 8;
    const uint32_t sbase = (uint32_t)__cvta_generic_to_shared(dsm);
    const uint32_t a_lds = sbase + (uint32_t)(((wr * 64 + mrow) * LDA + mcol) * 2);
    const uint32_t b_lds = sbase + (uint32_t)((ASZ + mrow * LDB + wc * 32 + mcol) * 2);

    #pragma unroll
    for (int s = 0; s < NST - 1; s++) {
        gemm_issue_stage(A, B, Bld, row0, col0, s * GBK, dsm + s * STAGE_H, a_m, a_k0, b_k, b_n0);
        CP_COMMIT();
    }

    for (int kt = 0; kt < KT; kt++) {
        CP_WAIT(NST - 2);
        __syncthreads();

        if (kt + NST - 1 < KT) {
            gemm_issue_stage(A, B, Bld, row0, col0, (kt + NST - 1) * GBK,
                             dsm + ((kt + NST - 1) % NST) * STAGE_H, a_m, a_k0, b_k, b_n0);
        }
        CP_COMMIT();

        const uint32_t stoff = (uint32_t)((kt % NST) * STAGE_H * 2);

        #pragma unroll
        for (int kb = 0; kb < GBK; kb += 16) {
            uint32_t af[4][4], bg[2][4];
            #pragma unroll
            for (int i = 0; i < 4; i++)
                LDSM_X4(af[i][0], af[i][1], af[i][2], af[i][3],
                        a_lds + stoff + (uint32_t)((i * 16 * LDA + kb) * 2));
            #pragma unroll
            for (int j2 = 0; j2 < 2; j2++)
                LDSM_X4T(bg[j2][0], bg[j2][1], bg[j2][2], bg[j2][3],
                         b_lds + stoff + (uint32_t)((kb * LDB + j2 * 16) * 2));
            #pragma unroll
            for (int i = 0; i < 4; i++)
                #pragma unroll
                for (int j = 0; j < 4; j++)
                    MMA_F16(c[i][j], af[i][0], af[i][1], af[i][2], af[i][3],
                            bg[j >> 1][(j & 1) * 2], bg[j >> 1][(j & 1) * 2 + 1]);
        }
    }
}

__global__ __launch_bounds__(256) void qkv_gemm_f16(
    const float* __restrict__ bq, const float* __restrict__ bk,
    const float* __restrict__ bv, const float* __restrict__ pos) {
    extern __shared__ __half dsm[];
    const int row0 = blockIdx.y * GBM;
    const int col0 = blockIdx.x * GBN;

    float c[4][4][4];
    #pragma unroll
    for (int i = 0; i < 4; i++)
        #pragma unroll
        for (int j = 0; j < 4; j++)
            #pragma unroll
            for (int q = 0; q < 4; q++) c[i][j][q] = 0.f;

    gemm_f16_mainloop(g_xnorm, g_Wqkv, NQKV, row0, col0, c, dsm);

    const int lane = threadIdx.x & 31;
    const int warp = threadIdx.x >> 5;
    const int wr = warp >> 2, wc = warp & 3;
    const int lq = lane & 3, lg = lane >> 2;

    const int which = col0 / DIM;
    const float* bias = (which == 0) ? bq : ((which == 1) ? bk : bv);
    __half* out = (which == 0) ? g_Q : ((which == 1) ? g_K : g_V);

    #pragma unroll
    for (int i = 0; i < 4; i++) {
        #pragma unroll
        for (int j = 0; j < 4; j++) {
            int cg = col0 + wc * 32 + j * 8 + 2 * lq;
            int nl = cg - which * DIM;
            float b0 = bias[nl], b1 = bias[nl + 1];
            int h = nl >> 6, d = nl & 63;
            #pragma unroll
            for (int rh = 0; rh < 2; rh++) {
                int m = row0 + wr * 64 + i * 16 + lg + rh * 8;
                float v0 = c[i][j][rh * 2 + 0] + b0;
                float v1 = c[i][j][rh * 2 + 1] + b1;
                if (which == 0) {
                    float2 p = *(const float2*)&pos[(size_t)m * DIM + nl];
                    v0 += p.x; v1 += p.y;
                }
                int bidx = m >> 10, n = m & 1023;
                *(half2*)&out[(size_t)((bidx * HEADS + h) * SEQ + n) * HDIM + d] =
                    __floats2half2_rn(v0, v1);
            }
        }
    }
}

__global__ __launch_bounds__(256) void out_gemm_f16(
    const float* __restrict__ bo, const float* __restrict__ x, float* __restrict__ out) {
    extern __shared__ __half dsm[];
    const int row0 = blockIdx.y * GBM;
    const int col0 = blockIdx.x * GBN;

    float c[4][4][4];
    #pragma unroll
    for (int i = 0; i < 4; i++)
        #pragma unroll
        for (int j = 0; j < 4; j++)
            #pragma unroll
            for (int q = 0; q < 4; q++) c[i][j][q] = 0.f;

    gemm_f16_mainloop(g_attn, g_Wo, DIM, row0, col0, c, dsm);

    const int lane = threadIdx.x & 31;
    const int warp = threadIdx.x >> 5;
    const int wr = warp >> 2, wc = warp & 3;
    const int lq = lane & 3, lg = lane >> 2;

    #pragma unroll
    for (int i = 0; i < 4; i++) {
        #pragma unroll
        for (int j = 0; j < 4; j++) {
            int cc = col0 + wc * 32 + j * 8 + 2 * lq;
            float b0 = bo[cc], b1 = bo[cc + 1];
            #pragma unroll
            for (int rh = 0; rh < 2; rh++) {
                int m = row0 + wr * 64 + i * 16 + lg + rh * 8;
                float2 xr = *(const float2*)&x[(size_t)m * DIM + cc];
                float2 r;
                r.x = c[i][j][rh * 2 + 0] + b0 + xr.x;
                r.y = c[i][j][rh * 2 + 1] + b1 + xr.y;
                *(float2*)&out[(size_t)m * DIM + cc] = r;
            }
        }
    }
}

// ---------------- FA2-style fp16 attention: warp = 16 queries x ALL 64 keys ----------------
// 128 queries/block, 8 warps. Softmax fully in registers (warp-local rows).
#define LDH 72

__global__ __launch_bounds__(256) void attn_f16_kernel() {
    __shared__ __align__(16) __half Qs[128 * LDH];
    __shared__ __align__(16) __half Ks[64 * LDH];
    __shared__ __align__(16) __half Vs[64 * LDH];

    const int t    = threadIdx.x;
    const int lane = t & 31;
    const int warp = t >> 5;
    const int lq   = lane & 3;
    const int lg   = lane >> 2;

    const int q0 = blockIdx.x * 128;
    const int bh = blockIdx.y;
    const __half* Qg = g_Q + (size_t)bh * SEQ * HDIM;
    const __half* Kg = g_K + (size_t)bh * SEQ * HDIM;
    const __half* Vg = g_V + (size_t)bh * SEQ * HDIM;

    // ldmatrix lane patterns
    const int mrow = ((lane >> 3) & 1) * 8 + (lane & 7);   // A / V-trans pattern
    const int mcol = (lane >> 4) * 8;
    const int nrow = (lane >> 4) * 8 + (lane & 7);         // K (B, non-trans) pattern
    const int kcol = ((lane >> 3) & 1) * 8;

    const uint32_t qs_u = (uint32_t)__cvta_generic_to_shared(Qs);
    const uint32_t ks_u = (uint32_t)__cvta_generic_to_shared(Ks);
    const uint32_t vs_u = (uint32_t)__cvta_generic_to_shared(Vs);

    // load Q tile [128][64]
    {
        int qr = t >> 1, qc = (t & 1) * 32;
        #pragma unroll
        for (int ii = 0; ii < 4; ii++)
            *(uint4*)&Qs[qr * LDH + qc + ii * 8] =
                *(const uint4*)&Qg[(size_t)(q0 + qr) * HDIM + qc + ii * 8];
    }
    __syncthreads();

    // hoist Q A-fragments (warp rows [warp*16, warp*16+16))
    uint32_t aq[4][4];
    {
        uint32_t abase = qs_u + (uint32_t)(((warp * 16 + mrow) * LDH + mcol) * 2);
        #pragma unroll
        for (int kb = 0; kb < 4; kb++)
            LDSM_X4(aq[kb][0], aq[kb][1], aq[kb][2], aq[kb][3],
                    abase + (uint32_t)(kb * 16 * 2));
    }

    // per-thread row state (rows lg and lg+8 of this warp's 16)
    float m0 = -1e30f, m1 = -1e30f, l0 = 0.f, l1 = 0.f;
    float o[8][4];
    #pragma unroll
    for (int j = 0; j < 8; j++)
        #pragma unroll
        for (int q = 0; q < 4; q++) o[j][q] = 0.f;

    const int lr  = t >> 2;          // 0..63
    const int lc0 = (t & 3) * 16;

    for (int n0 = 0; n0 < SEQ; n0 += 64) {
        // load K,V tiles [64][64]
        *(uint4*)&Ks[lr * LDH + lc0]     = *(const uint4*)&Kg[(size_t)(n0 + lr) * HDIM + lc0];
        *(uint4*)&Ks[lr * LDH + lc0 + 8] = *(const uint4*)&Kg[(size_t)(n0 + lr) * HDIM + lc0 + 8];
        *(uint4*)&Vs[lr * LDH + lc0]     = *(const uint4*)&Vg[(size_t)(n0 + lr) * HDIM + lc0];
        *(uint4*)&Vs[lr * LDH + lc0 + 8] = *(const uint4*)&Vg[(size_t)(n0 + lr) * HDIM + lc0 + 8];
        __syncthreads();

        // S = Q @ K^T : c4[8 n-frags][4], all 64 keys in this warp
        float c4[8][4];
        #pragma unroll
        for (int j = 0; j < 8; j++)
            #pragma unroll
            for (int q = 0; q < 4; q++) c4[j][q] = 0.f;
        #pragma unroll
        for (int kb = 0; kb < 4; kb++) {
            #pragma unroll
            for (int j2 = 0; j2 < 4; j2++) {
                uint32_t bf0, bf1, bf2, bf3;
                LDSM_X4(bf0, bf1, bf2, bf3,
                        ks_u + (uint32_t)(((j2 * 16 + nrow) * LDH + kb * 16 + kcol) * 2));
                MMA_F16(c4[2 * j2],     aq[kb][0], aq[kb][1], aq[kb][2], aq[kb][3], bf0, bf1);
                MMA_F16(c4[2 * j2 + 1], aq[kb][0], aq[kb][1], aq[kb][2], aq[kb][3], bf2, bf3);
            }
        }
        #pragma unroll
        for (int j = 0; j < 8; j++) {
            c4[j][0] *= 0.125f; c4[j][1] *= 0.125f;
            c4[j][2] *= 0.125f; c4[j][3] *= 0.125f;
        }

        // warp-local row max (rows lg, lg+8)
        float tm0 = -1e30f, tm1 = -1e30f;
        #pragma unroll
        for (int j = 0; j < 8; j++) {
            tm0 = fmaxf(tm0, fmaxf(c4[j][0], c4[j][1]));
            tm1 = fmaxf(tm1, fmaxf(c4[j][2], c4[j][3]));
        }
        tm0 = fmaxf(tm0, __shfl_xor_sync(0xffffffffu, tm0, 1));
        tm0 = fmaxf(tm0, __shfl_xor_sync(0xffffffffu, tm0, 2));
        tm1 = fmaxf(tm1, __shfl_xor_sync(0xffffffffu, tm1, 1));
        tm1 = fmaxf(tm1, __shfl_xor_sync(0xffffffffu, tm1, 2));

        float mn0 = fmaxf(m0, tm0), mn1 = fmaxf(m1, tm1);
        float al0 = __expf(m0 - mn0), al1 = __expf(m1 - mn1);
        m0 = mn0; m1 = mn1;

        // exp in registers + pack P A-frags + row sums
        uint32_t ap[4][4];
        float s0 = 0.f, s1 = 0.f;
        #pragma unroll
        for (int kk = 0; kk < 4; kk++) {
            float e00 = __expf(c4[2 * kk][0] - mn0);
            float e01 = __expf(c4[2 * kk][1] - mn0);
            float e02 = __expf(c4[2 * kk][2] - mn1);
            float e03 = __expf(c4[2 * kk][3] - mn1);
            float e10 = __expf(c4[2 * kk + 1][0] - mn0);
            float e11 = __expf(c4[2 * kk + 1][1] - mn0);
            float e12 = __expf(c4[2 * kk + 1][2] - mn1);
            float e13 = __expf(c4[2 * kk + 1][3] - mn1);
            s0 += e00 + e01 + e10 + e11;
            s1 += e02 + e03 + e12 + e13;
            half2 h;
            h = __floats2half2_rn(e00, e01); ap[kk][0] = *(uint32_t*)&h;
            h = __floats2half2_rn(e02, e03); ap[kk][1] = *(uint32_t*)&h;
            h = __floats2half2_rn(e10, e11); ap[kk][2] = *(uint32_t*)&h;
            h = __floats2half2_rn(e12, e13); ap[kk][3] = *(uint32_t*)&h;
        }
        s0 += __shfl_xor_sync(0xffffffffu, s0, 1);
        s0 += __shfl_xor_sync(0xffffffffu, s0, 2);
        s1 += __shfl_xor_sync(0xffffffffu, s1, 1);
        s1 += __shfl_xor_sync(0xffffffffu, s1, 2);
        l0 = l0 * al0 + s0;
        l1 = l1 * al1 + s1;

        // rescale O
        #pragma unroll
        for (int j = 0; j < 8; j++) {
            o[j][0] *= al0; o[j][1] *= al0;
            o[j][2] *= al1; o[j][3] *= al1;
        }

        // O += P @ V  (B-frags from Vs[n][d] via ldmatrix trans)
        #pragma unroll
        for (int kk = 0; kk < 4; kk++) {
            #pragma unroll
            for (int j2 = 0; j2 < 4; j2++) {
                uint32_t bf0, bf1, bf2, bf3;
                LDSM_X4T(bf0, bf1, bf2, bf3,
                         vs_u + (uint32_t)(((kk * 16 + mrow) * LDH + j2 * 16 + mcol) * 2));
                MMA_F16(o[2 * j2],     ap[kk][0], ap[kk][1], ap[kk][2], ap[kk][3], bf0, bf1);
                MMA_F16(o[2 * j2 + 1], ap[kk][0], ap[kk][1], ap[kk][2], ap[kk][3], bf2, bf3);
            }
        }
        __syncthreads();
    }

    // normalize + write to (B,N,C)
    const int b = bh / HEADS;
    const int h = bh % HEADS;
    float inv0 = 1.0f / l0, inv1 = 1.0f / l1;
    int r0 = q0 + warp * 16 + lg;
    #pragma unroll
    for (int j = 0; j < 8; j++) {
        int d = j * 8 + 2 * lq;
        *(half2*)&g_attn[(size_t)(b * SEQ + r0) * DIM + h * HDIM + d] =
            __floats2half2_rn(o[j][0] * inv0, o[j][1] * inv0);
        *(half2*)&g_attn[(size_t)(b * SEQ + r0 + 8) * DIM + h * HDIM + d] =
            __floats2half2_rn(o[j][2] * inv1, o[j][3] * inv1);
    }
}

// ---------------- launcher ----------------
extern "C" void kernel_launch(void* const* d_in, const int* in_sizes, int n_in,
                              void* d_out, int out_size) {
    const float* x     = (const float*)d_in[0];
    const float* pos   = (const float*)d_in[1];
    const float* gamma = (const float*)d_in[2];
    const float* beta  = (const float*)d_in[3];
    const float* Wq    = (const float*)d_in[4];
    const float* bq    = (const float*)d_in[5];
    const float* Wk    = (const float*)d_in[6];
    const float* bk    = (const float*)d_in[7];
    const float* Wv    = (const float*)d_in[8];
    const float* bv    = (const float*)d_in[9];
    const float* Wo    = (const float*)d_in[10];
    const float* bo    = (const float*)d_in[11];
    float* out = (float*)d_out;

    cudaFuncSetAttribute(qkv_gemm_f16, cudaFuncAttributeMaxDynamicSharedMemorySize, GEMM_SMEM_BYTES);
    cudaFuncSetAttribute(out_gemm_f16, cudaFuncAttributeMaxDynamicSharedMemorySize, GEMM_SMEM_BYTES);

    convert_wqkv<<<DIM * NQKV / 1024, 256>>>(Wq, Wk, Wv);
    convert_wo<<<DIM * DIM / 1024, 256>>>(Wo);
    ln_kernel<<<ROWS / 8, 256>>>(x, gamma, beta);
    qkv_gemm_f16<<<dim3(NQKV / GBN, ROWS / GBM), 256, GEMM_SMEM_BYTES>>>(bq, bk, bv, pos);
    attn_f16_kernel<<<dim3(SEQ / 128, BATCH * HEADS), 256>>>();
    out_gemm_f16<<<dim3(DIM / GBN, ROWS / GBM), 256, GEMM_SMEM_BYTES>>>(bo, x, out);
}

// round 11
// speedup vs baseline: 5.9083x; 1.0384x over previous
#include <cuda_runtime.h>
#include <cuda_fp16.h>
#include <cstdint>

#define DIM   768
#define HEADS 12
#define HDIM  64
#define SEQ   1024
#define BATCH 8
#define ROWS  (BATCH*SEQ)   // 8192
#define NQKV  (3*DIM)       // 2304
#define LN_EPS 1e-5f

// ---------------- scratch (fp16 datapath) ----------------
__device__ __half g_xnorm[ROWS*DIM];
__device__ __half g_Q[ROWS*DIM];      // (B,H,N,D)
__device__ __half g_K[ROWS*DIM];
__device__ __half g_V[ROWS*DIM];
__device__ __half g_attn[ROWS*DIM];   // (B,N,C)
__device__ __half g_Wqkv[DIM*NQKV];   // [k][3*768] concat Q|K|V
__device__ __half g_Wo[DIM*DIM];      // [k][n]

// ---------------- helpers ----------------
__device__ __forceinline__ void cp_async16(void* smem_ptr, const void* gptr) {
    uint32_t sa = (uint32_t)__cvta_generic_to_shared(smem_ptr);
    asm volatile("cp.async.cg.shared.global [%0], [%1], 16;" :: "r"(sa), "l"(gptr));
}
#define CP_COMMIT()  asm volatile("cp.async.commit_group;")
#define CP_WAIT(n)   asm volatile("cp.async.wait_group %0;" :: "n"(n))

#define LDSM_X4(d0,d1,d2,d3,addr) \
  asm volatile("ldmatrix.sync.aligned.m8n8.x4.shared.b16 {%0,%1,%2,%3}, [%4];" \
    : "=r"(d0), "=r"(d1), "=r"(d2), "=r"(d3) : "r"(addr))
#define LDSM_X4T(d0,d1,d2,d3,addr) \
  asm volatile("ldmatrix.sync.aligned.m8n8.x4.trans.shared.b16 {%0,%1,%2,%3}, [%4];" \
    : "=r"(d0), "=r"(d1), "=r"(d2), "=r"(d3) : "r"(addr))

#define MMA_F16(c, a0,a1,a2,a3, b0,b1) \
  asm volatile("mma.sync.aligned.m16n8k16.row.col.f32.f16.f16.f32 " \
    "{%0,%1,%2,%3}, {%4,%5,%6,%7}, {%8,%9}, {%0,%1,%2,%3};" \
    : "+f"((c)[0]), "+f"((c)[1]), "+f"((c)[2]), "+f"((c)[3]) \
    : "r"(a0), "r"(a1), "r"(a2), "r"(a3), "r"(b0), "r"(b1))

// ---------------- weight conversion ----------------
__global__ __launch_bounds__(256) void convert_wqkv(const float* __restrict__ Wq,
                                                    const float* __restrict__ Wk,
                                                    const float* __restrict__ Wv) {
    int idx = (blockIdx.x * 256 + threadIdx.x) * 4;
    int k = idx / NQKV, ng = idx - k * NQKV;
    int which = ng / DIM, n = ng - which * DIM;
    const float* W = (which == 0) ? Wq : ((which == 1) ? Wk : Wv);
    float4 v = *(const float4*)&W[(size_t)k * DIM + n];
    __half* dst = &g_Wqkv[(size_t)k * NQKV + ng];
    *(half2*)dst       = __floats2half2_rn(v.x, v.y);
    *(half2*)(dst + 2) = __floats2half2_rn(v.z, v.w);
}
__global__ __launch_bounds__(256) void convert_wo(const float* __restrict__ Wo) {
    int idx = (blockIdx.x * 256 + threadIdx.x) * 4;
    float4 v = *(const float4*)&Wo[idx];
    __half* dst = &g_Wo[idx];
    *(half2*)dst       = __floats2half2_rn(v.x, v.y);
    *(half2*)(dst + 2) = __floats2half2_rn(v.z, v.w);
}

// ---------------- LayerNorm: warp per row, fp16 out ----------------
__global__ __launch_bounds__(256) void ln_kernel(const float* __restrict__ x,
                                                 const float* __restrict__ gamma,
                                                 const float* __restrict__ beta) {
    int row  = blockIdx.x * 8 + (threadIdx.x >> 5);
    int lane = threadIdx.x & 31;
    const float* xr = x + (size_t)row * DIM;
    float4 v[6];
    float s = 0.f, sq = 0.f;
    #pragma unroll
    for (int i = 0; i < 6; i++) {
        v[i] = *(const float4*)&xr[(i * 32 + lane) * 4];
        s  += v[i].x + v[i].y + v[i].z + v[i].w;
        sq += v[i].x * v[i].x + v[i].y * v[i].y + v[i].z * v[i].z + v[i].w * v[i].w;
    }
    #pragma unroll
    for (int o = 16; o > 0; o >>= 1) {
        s  += __shfl_xor_sync(0xffffffffu, s, o);
        sq += __shfl_xor_sync(0xffffffffu, sq, o);
    }
    float mu  = s * (1.0f / DIM);
    float var = sq * (1.0f / DIM) - mu * mu;
    float inv = rsqrtf(var + LN_EPS);
    __half* orow = g_xnorm + (size_t)row * DIM;
    #pragma unroll
    for (int i = 0; i < 6; i++) {
        int c = (i * 32 + lane) * 4;
        float4 g = *(const float4*)&gamma[c];
        float4 b = *(const float4*)&beta[c];
        *(half2*)&orow[c]     = __floats2half2_rn((v[i].x - mu) * inv * g.x + b.x,
                                                  (v[i].y - mu) * inv * g.y + b.y);
        *(half2*)&orow[c + 2] = __floats2half2_rn((v[i].z - mu) * inv * g.z + b.z,
                                                  (v[i].w - mu) * inv * g.w + b.w);
    }
}

// ---------------- fp16 GEMM: 4-stage cp.async + ldmatrix (unchanged from R8) ----------------
#define GBM 128
#define GBN 128
#define GBK 32
#define NST 4
#define LDA 40
#define LDB 136
#define ASZ (GBM*LDA)
#define BSZ (GBK*LDB)
#define STAGE_H (ASZ + BSZ)
#define GEMM_SMEM_BYTES (NST * STAGE_H * 2)
#define KT (DIM / GBK)

__device__ __forceinline__ void gemm_issue_stage(
    const __half* __restrict__ A, const __half* __restrict__ B, int Bld,
    int row0, int col0, int k0, __half* stage,
    int a_m, int a_k0, int b_k, int b_n0) {
    __half* As = stage;
    __half* Bs = stage + ASZ;
    cp_async16(&As[a_m * LDA + a_k0],     &A[(size_t)(row0 + a_m) * DIM + k0 + a_k0]);
    cp_async16(&As[a_m * LDA + a_k0 + 8], &A[(size_t)(row0 + a_m) * DIM + k0 + a_k0 + 8]);
    cp_async16(&Bs[b_k * LDB + b_n0],     &B[(size_t)(k0 + b_k) * Bld + col0 + b_n0]);
    cp_async16(&Bs[b_k * LDB + b_n0 + 8], &B[(size_t)(k0 + b_k) * Bld + col0 + b_n0 + 8]);
}

__device__ __forceinline__ void gemm_f16_mainloop(
    const __half* __restrict__ A, const __half* __restrict__ B, int Bld,
    int row0, int col0, float c[4][4][4], __half* dsm) {
    const int t    = threadIdx.x;
    const int lane = t & 31;
    const int warp = t >> 5;
    const int wr   = warp >> 2;
    const int wc   = warp & 3;

    const int a_m  = t >> 1;
    const int a_k0 = (t & 1) * 16;
    const int b_k  = t >> 3;
    const int b_n0 = (t & 7) * 16;

    const int mrow = ((lane >> 3) & 1) * 8 + (lane & 7);
    const int mcol = (lane >> 4) * 8;
    const uint32_t sbase = (uint32_t)__cvta_generic_to_shared(dsm);
    const uint32_t a_lds = sbase + (uint32_t)(((wr * 64 + mrow) * LDA + mcol) * 2);
    const uint32_t b_lds = sbase + (uint32_t)((ASZ + mrow * LDB + wc * 32 + mcol) * 2);

    #pragma unroll
    for (int s = 0; s < NST - 1; s++) {
        gemm_issue_stage(A, B, Bld, row0, col0, s * GBK, dsm + s * STAGE_H, a_m, a_k0, b_k, b_n0);
        CP_COMMIT();
    }

    for (int kt = 0; kt < KT; kt++) {
        CP_WAIT(NST - 2);
        __syncthreads();

        if (kt + NST - 1 < KT) {
            gemm_issue_stage(A, B, Bld, row0, col0, (kt + NST - 1) * GBK,
                             dsm + ((kt + NST - 1) % NST) * STAGE_H, a_m, a_k0, b_k, b_n0);
        }
        CP_COMMIT();

        const uint32_t stoff = (uint32_t)((kt % NST) * STAGE_H * 2);

        #pragma unroll
        for (int kb = 0; kb < GBK; kb += 16) {
            uint32_t af[4][4], bg[2][4];
            #pragma unroll
            for (int i = 0; i < 4; i++)
                LDSM_X4(af[i][0], af[i][1], af[i][2], af[i][3],
                        a_lds + stoff + (uint32_t)((i * 16 * LDA + kb) * 2));
            #pragma unroll
            for (int j2 = 0; j2 < 2; j2++)
                LDSM_X4T(bg[j2][0], bg[j2][1], bg[j2][2], bg[j2][3],
                         b_lds + stoff + (uint32_t)((kb * LDB + j2 * 16) * 2));
            #pragma unroll
            for (int i = 0; i < 4; i++)
                #pragma unroll
                for (int j = 0; j < 4; j++)
                    MMA_F16(c[i][j], af[i][0], af[i][1], af[i][2], af[i][3],
                            bg[j >> 1][(j & 1) * 2], bg[j >> 1][(j & 1) * 2 + 1]);
        }
    }
}

__global__ __launch_bounds__(256) void qkv_gemm_f16(
    const float* __restrict__ bq, const float* __restrict__ bk,
    const float* __restrict__ bv, const float* __restrict__ pos) {
    extern __shared__ __half dsm[];
    const int row0 = blockIdx.y * GBM;
    const int col0 = blockIdx.x * GBN;

    float c[4][4][4];
    #pragma unroll
    for (int i = 0; i < 4; i++)
        #pragma unroll
        for (int j = 0; j < 4; j++)
            #pragma unroll
            for (int q = 0; q < 4; q++) c[i][j][q] = 0.f;

    gemm_f16_mainloop(g_xnorm, g_Wqkv, NQKV, row0, col0, c, dsm);

    const int lane = threadIdx.x & 31;
    const int warp = threadIdx.x >> 5;
    const int wr = warp >> 2, wc = warp & 3;
    const int lq = lane & 3, lg = lane >> 2;

    const int which = col0 / DIM;
    const float* bias = (which == 0) ? bq : ((which == 1) ? bk : bv);
    __half* out = (which == 0) ? g_Q : ((which == 1) ? g_K : g_V);

    #pragma unroll
    for (int i = 0; i < 4; i++) {
        #pragma unroll
        for (int j = 0; j < 4; j++) {
            int cg = col0 + wc * 32 + j * 8 + 2 * lq;
            int nl = cg - which * DIM;
            float b0 = bias[nl], b1 = bias[nl + 1];
            int h = nl >> 6, d = nl & 63;
            #pragma unroll
            for (int rh = 0; rh < 2; rh++) {
                int m = row0 + wr * 64 + i * 16 + lg + rh * 8;
                float v0 = c[i][j][rh * 2 + 0] + b0;
                float v1 = c[i][j][rh * 2 + 1] + b1;
                if (which == 0) {
                    float2 p = *(const float2*)&pos[(size_t)m * DIM + nl];
                    v0 += p.x; v1 += p.y;
                }
                int bidx = m >> 10, n = m & 1023;
                *(half2*)&out[(size_t)((bidx * HEADS + h) * SEQ + n) * HDIM + d] =
                    __floats2half2_rn(v0, v1);
            }
        }
    }
}

__global__ __launch_bounds__(256) void out_gemm_f16(
    const float* __restrict__ bo, const float* __restrict__ x, float* __restrict__ out) {
    extern __shared__ __half dsm[];
    const int row0 = blockIdx.y * GBM;
    const int col0 = blockIdx.x * GBN;

    float c[4][4][4];
    #pragma unroll
    for (int i = 0; i < 4; i++)
        #pragma unroll
        for (int j = 0; j < 4; j++)
            #pragma unroll
            for (int q = 0; q < 4; q++) c[i][j][q] = 0.f;

    gemm_f16_mainloop(g_attn, g_Wo, DIM, row0, col0, c, dsm);

    const int lane = threadIdx.x & 31;
    const int warp = threadIdx.x >> 5;
    const int wr = warp >> 2, wc = warp & 3;
    const int lq = lane & 3, lg = lane >> 2;

    #pragma unroll
    for (int i = 0; i < 4; i++) {
        #pragma unroll
        for (int j = 0; j < 4; j++) {
            int cc = col0 + wc * 32 + j * 8 + 2 * lq;
            float b0 = bo[cc], b1 = bo[cc + 1];
            #pragma unroll
            for (int rh = 0; rh < 2; rh++) {
                int m = row0 + wr * 64 + i * 16 + lg + rh * 8;
                float2 xr = *(const float2*)&x[(size_t)m * DIM + cc];
                float2 r;
                r.x = c[i][j][rh * 2 + 0] + b0 + xr.x;
                r.y = c[i][j][rh * 2 + 1] + b1 + xr.y;
                *(float2*)&out[(size_t)m * DIM + cc] = r;
            }
        }
    }
}

// ---------------- FA2-style fp16 attention + cp.async double-buffered K/V ----------------
#define LDH 72
#define QS_H   (128 * LDH)            // 9216 halfs
#define KV_H   (64 * LDH)             // 4608 halfs per K or V buffer
#define STG_H  (2 * KV_H)             // K+V per stage
#define ATTN_SMEM_BYTES ((QS_H + 2 * STG_H) * 2)   // 55296 B
#define NT (SEQ / 64)                 // 16 key tiles

__global__ __launch_bounds__(256) void attn_f16_kernel() {
    extern __shared__ __align__(16) __half asm_[];
    __half* Qs = asm_;

    const int t    = threadIdx.x;
    const int lane = t & 31;
    const int warp = t >> 5;
    const int lq   = lane & 3;
    const int lg   = lane >> 2;

    const int q0 = blockIdx.x * 128;
    const int bh = blockIdx.y;
    const __half* Qg = g_Q + (size_t)bh * SEQ * HDIM;
    const __half* Kg = g_K + (size_t)bh * SEQ * HDIM;
    const __half* Vg = g_V + (size_t)bh * SEQ * HDIM;

    const int mrow = ((lane >> 3) & 1) * 8 + (lane & 7);
    const int mcol = (lane >> 4) * 8;
    const int nrow = (lane >> 4) * 8 + (lane & 7);
    const int kcol = ((lane >> 3) & 1) * 8;

    const uint32_t smem_u = (uint32_t)__cvta_generic_to_shared(asm_);
    const uint32_t qs_u = smem_u;

    const int lr  = t >> 2;          // 0..63
    const int lc0 = (t & 3) * 16;    // 0,16,32,48

    // issue K0/V0 prefetch before loading Q (overlap)
    {
        __half* K0 = asm_ + QS_H;
        __half* V0 = K0 + KV_H;
        const __half* ks = Kg + (size_t)lr * HDIM + lc0;
        const __half* vs = Vg + (size_t)lr * HDIM + lc0;
        cp_async16(&K0[lr * LDH + lc0],     ks);
        cp_async16(&K0[lr * LDH + lc0 + 8], ks + 8);
        cp_async16(&V0[lr * LDH + lc0],     vs);
        cp_async16(&V0[lr * LDH + lc0 + 8], vs + 8);
        CP_COMMIT();
    }

    // load Q tile [128][64]
    {
        int qr = t >> 1, qc = (t & 1) * 32;
        #pragma unroll
        for (int ii = 0; ii < 4; ii++)
            *(uint4*)&Qs[qr * LDH + qc + ii * 8] =
                *(const uint4*)&Qg[(size_t)(q0 + qr) * HDIM + qc + ii * 8];
    }
    __syncthreads();

    // hoist Q A-fragments (warp rows [warp*16, warp*16+16))
    uint32_t aq[4][4];
    {
        uint32_t abase = qs_u + (uint32_t)(((warp * 16 + mrow) * LDH + mcol) * 2);
        #pragma unroll
        for (int kb = 0; kb < 4; kb++)
            LDSM_X4(aq[kb][0], aq[kb][1], aq[kb][2], aq[kb][3],
                    abase + (uint32_t)(kb * 16 * 2));
    }

    float m0 = -1e30f, m1 = -1e30f, l0 = 0.f, l1 = 0.f;
    float o[8][4];
    #pragma unroll
    for (int j = 0; j < 8; j++)
        #pragma unroll
        for (int q = 0; q < 4; q++) o[j][q] = 0.f;

    for (int kt = 0; kt < NT; kt++) {
        const int cur = kt & 1;
        // prefetch next tile into the other stage
        if (kt + 1 < NT) {
            __half* Kn = asm_ + QS_H + (cur ^ 1) * STG_H;
            __half* Vn = Kn + KV_H;
            const __half* ks = Kg + (size_t)((kt + 1) * 64 + lr) * HDIM + lc0;
            const __half* vs = Vg + (size_t)((kt + 1) * 64 + lr) * HDIM + lc0;
            cp_async16(&Kn[lr * LDH + lc0],     ks);
            cp_async16(&Kn[lr * LDH + lc0 + 8], ks + 8);
            cp_async16(&Vn[lr * LDH + lc0],     vs);
            cp_async16(&Vn[lr * LDH + lc0 + 8], vs + 8);
            CP_COMMIT();
            CP_WAIT(1);       // current tile's group retired; prefetch may run
        } else {
            CP_WAIT(0);
        }
        __syncthreads();

        const uint32_t ks_u = smem_u + (uint32_t)((QS_H + cur * STG_H) * 2);
        const uint32_t vs_u = ks_u + (uint32_t)(KV_H * 2);

        // S = Q @ K^T : all 64 keys in this warp
        float c4[8][4];
        #pragma unroll
        for (int j = 0; j < 8; j++)
            #pragma unroll
            for (int q = 0; q < 4; q++) c4[j][q] = 0.f;
        #pragma unroll
        for (int kb = 0; kb < 4; kb++) {
            #pragma unroll
            for (int j2 = 0; j2 < 4; j2++) {
                uint32_t bf0, bf1, bf2, bf3;
                LDSM_X4(bf0, bf1, bf2, bf3,
                        ks_u + (uint32_t)(((j2 * 16 + nrow) * LDH + kb * 16 + kcol) * 2));
                MMA_F16(c4[2 * j2],     aq[kb][0], aq[kb][1], aq[kb][2], aq[kb][3], bf0, bf1);
                MMA_F16(c4[2 * j2 + 1], aq[kb][0], aq[kb][1], aq[kb][2], aq[kb][3], bf2, bf3);
            }
        }
        #pragma unroll
        for (int j = 0; j < 8; j++) {
            c4[j][0] *= 0.125f; c4[j][1] *= 0.125f;
            c4[j][2] *= 0.125f; c4[j][3] *= 0.125f;
        }

        // warp-local row max
        float tm0 = -1e30f, tm1 = -1e30f;
        #pragma unroll
        for (int j = 0; j < 8; j++) {
            tm0 = fmaxf(tm0, fmaxf(c4[j][0], c4[j][1]));
            tm1 = fmaxf(tm1, fmaxf(c4[j][2], c4[j][3]));
        }
        tm0 = fmaxf(tm0, __shfl_xor_sync(0xffffffffu, tm0, 1));
        tm0 = fmaxf(tm0, __shfl_xor_sync(0xffffffffu, tm0, 2));
        tm1 = fmaxf(tm1, __shfl_xor_sync(0xffffffffu, tm1, 1));
        tm1 = fmaxf(tm1, __shfl_xor_sync(0xffffffffu, tm1, 2));

        float mn0 = fmaxf(m0, tm0), mn1 = fmaxf(m1, tm1);
        float al0 = __expf(m0 - mn0), al1 = __expf(m1 - mn1);
        m0 = mn0; m1 = mn1;

        // exp in registers + pack P A-frags + row sums
        uint32_t ap[4][4];
        float s0 = 0.f, s1 = 0.f;
        #pragma unroll
        for (int kk = 0; kk < 4; kk++) {
            float e00 = __expf(c4[2 * kk][0] - mn0);
            float e01 = __expf(c4[2 * kk][1] - mn0);
            float e02 = __expf(c4[2 * kk][2] - mn1);
            float e03 = __expf(c4[2 * kk][3] - mn1);
            float e10 = __expf(c4[2 * kk + 1][0] - mn0);
            float e11 = __expf(c4[2 * kk + 1][1] - mn0);
            float e12 = __expf(c4[2 * kk + 1][2] - mn1);
            float e13 = __expf(c4[2 * kk + 1][3] - mn1);
            s0 += e00 + e01 + e10 + e11;
            s1 += e02 + e03 + e12 + e13;
            half2 h;
            h = __floats2half2_rn(e00, e01); ap[kk][0] = *(uint32_t*)&h;
            h = __floats2half2_rn(e02, e03); ap[kk][1] = *(uint32_t*)&h;
            h = __floats2half2_rn(e10, e11); ap[kk][2] = *(uint32_t*)&h;
            h = __floats2half2_rn(e12, e13); ap[kk][3] = *(uint32_t*)&h;
        }
        s0 += __shfl_xor_sync(0xffffffffu, s0, 1);
        s0 += __shfl_xor_sync(0xffffffffu, s0, 2);
        s1 += __shfl_xor_sync(0xffffffffu, s1, 1);
        s1 += __shfl_xor_sync(0xffffffffu, s1, 2);
        l0 = l0 * al0 + s0;
        l1 = l1 * al1 + s1;

        // rescale O
        #pragma unroll
        for (int j = 0; j < 8; j++) {
            o[j][0] *= al0; o[j][1] *= al0;
            o[j][2] *= al1; o[j][3] *= al1;
        }

        // O += P @ V
        #pragma unroll
        for (int kk = 0; kk < 4; kk++) {
            #pragma unroll
            for (int j2 = 0; j2 < 4; j2++) {
                uint32_t bf0, bf1, bf2, bf3;
                LDSM_X4T(bf0, bf1, bf2, bf3,
                         vs_u + (uint32_t)(((kk * 16 + mrow) * LDH + j2 * 16 + mcol) * 2));
                MMA_F16(o[2 * j2],     ap[kk][0], ap[kk][1], ap[kk][2], ap[kk][3], bf0, bf1);
                MMA_F16(o[2 * j2 + 1], ap[kk][0], ap[kk][1], ap[kk][2], ap[kk][3], bf2, bf3);
            }
        }
        __syncthreads();   // protect buffer reuse before next prefetch issue
    }

    // normalize + write to (B,N,C)
    const int b = bh / HEADS;
    const int h = bh % HEADS;
    float inv0 = 1.0f / l0, inv1 = 1.0f / l1;
    int r0 = q0 + warp * 16 + lg;
    #pragma unroll
    for (int j = 0; j < 8; j++) {
        int d = j * 8 + 2 * lq;
        *(half2*)&g_attn[(size_t)(b * SEQ + r0) * DIM + h * HDIM + d] =
            __floats2half2_rn(o[j][0] * inv0, o[j][1] * inv0);
        *(half2*)&g_attn[(size_t)(b * SEQ + r0 + 8) * DIM + h * HDIM + d] =
            __floats2half2_rn(o[j][2] * inv1, o[j][3] * inv1);
    }
}

// ---------------- launcher ----------------
extern "C" void kernel_launch(void* const* d_in, const int* in_sizes, int n_in,
                              void* d_out, int out_size) {
    const float* x     = (const float*)d_in[0];
    const float* pos   = (const float*)d_in[1];
    const float* gamma = (const float*)d_in[2];
    const float* beta  = (const float*)d_in[3];
    const float* Wq    = (const float*)d_in[4];
    const float* bq    = (const float*)d_in[5];
    const float* Wk    = (const float*)d_in[6];
    const float* bk    = (const float*)d_in[7];
    const float* Wv    = (const float*)d_in[8];
    const float* bv    = (const float*)d_in[9];
    const float* Wo    = (const float*)d_in[10];
    const float* bo    = (const float*)d_in[11];
    float* out = (float*)d_out;

    cudaFuncSetAttribute(qkv_gemm_f16, cudaFuncAttributeMaxDynamicSharedMemorySize, GEMM_SMEM_BYTES);
    cudaFuncSetAttribute(out_gemm_f16, cudaFuncAttributeMaxDynamicSharedMemorySize, GEMM_SMEM_BYTES);
    cudaFuncSetAttribute(attn_f16_kernel, cudaFuncAttributeMaxDynamicSharedMemorySize, ATTN_SMEM_BYTES);

    convert_wqkv<<<DIM * NQKV / 1024, 256>>>(Wq, Wk, Wv);
    convert_wo<<<DIM * DIM / 1024, 256>>>(Wo);
    ln_kernel<<<ROWS / 8, 256>>>(x, gamma, beta);
    qkv_gemm_f16<<<dim3(NQKV / GBN, ROWS / GBM), 256, GEMM_SMEM_BYTES>>>(bq, bk, bv, pos);
    attn_f16_kernel<<<dim3(SEQ / 128, BATCH * HEADS), 256, ATTN_SMEM_BYTES>>>();
    out_gemm_f16<<<dim3(DIM / GBN, ROWS / GBM), 256, GEMM_SMEM_BYTES>>>(bo, x, out);
}